// round 10
// baseline (speedup 1.0000x reference)
#include <cuda_runtime.h>
#include <cuda_fp16.h>

#define NMAX 100000
#define HDIM 64
#define SLOTS 128     // max degree safety: Poisson(32) max over 100k nodes ~58

// ---- device scratch (no allocations allowed), 16B-aligned ----
__device__ __align__(16) int     d_cnt [NMAX];
__device__ __align__(16) int     d_adj [(size_t)NMAX * SLOTS];  // padded adjacency
__device__ __align__(16) float   d_dinv[NMAX];
__device__ __align__(16) __half2 d_gh[(size_t)NMAX * (HDIM / 2)]; // gather source, fp16 (dinv-folded)
__device__ __align__(16) float   d_S [(size_t)NMAX * HDIM];     // propagate result (fp32)

#define BUF_EXT 0
#define BUF_S   1

// ---- packed f32x2 helpers (Blackwell FFMA2 via PTX) ----
typedef unsigned long long ull;
__device__ __forceinline__ ull pack2(float lo, float hi) {
    ull r; asm("mov.b64 %0, {%1, %2};" : "=l"(r) : "f"(lo), "f"(hi)); return r;
}
__device__ __forceinline__ ull dup2(float v) {
    ull r; asm("mov.b64 %0, {%1, %1};" : "=l"(r) : "f"(v)); return r;
}
__device__ __forceinline__ void unpack2(ull v, float& lo, float& hi) {
    asm("mov.b64 {%0, %1}, %2;" : "=f"(lo), "=f"(hi) : "l"(v));
}
__device__ __forceinline__ void fma2(ull& d, ull a, ull b) {
    asm("fma.rn.f32x2 %0, %1, %2, %3;" : "=l"(d) : "l"(a), "l"(b), "l"(d));
}
__device__ __forceinline__ __half2 u2h2(unsigned int u) {
    __half2 h; *(unsigned int*)&h = u; return h;
}

// ------------------------------------------------------------------
// adjacency build (edge_index is int32: JAX x64 disabled)
// ------------------------------------------------------------------
__global__ void zero_cnt_kernel(int n) {
    int i = blockIdx.x * blockDim.x + threadIdx.x;
    if (i < n) d_cnt[i] = 0;
}

__global__ void fill_adj_kernel(const int* __restrict__ e0,
                                const int* __restrict__ e1, int E) {
    int e = blockIdx.x * blockDim.x + threadIdx.x;
    if (e >= E) return;
    int u = __ldg(&e0[e]);
    int v = __ldg(&e1[e]);
    int pu = atomicAdd(&d_cnt[u], 1);
    if (pu < SLOTS) d_adj[(size_t)u * SLOTS + pu] = v;
    int pv = atomicAdd(&d_cnt[v], 1);
    if (pv < SLOTS) d_adj[(size_t)v * SLOTS + pv] = u;
}

// ------------------------------------------------------------------
// propagate (gather-only): S[i] = sum_{j in adj[i]} g[j]
// warp per node; quarter-warp s owns a neighbor substream; lane covers
// 8 cols via one LDG.128 (4 neighbor rows per warp-wide load).
// fp16 accumulation within a 4-neighbor group, fp32 flush per group.
// ------------------------------------------------------------------
__global__ __launch_bounds__(256)
void gather_kernel(int nn) {
    int node = blockIdx.x * 8 + (threadIdx.x >> 5);
    int lane = threadIdx.x & 31;
    if (node >= nn) return;
    int s = lane >> 3;         // substream 0..3
    int c = lane & 7;          // column octet: cols 8c..8c+7
    int cnt = min(d_cnt[node], SLOTS);
    const int* adj = &d_adj[(size_t)node * SLOTS];
    const uint4* gh4 = (const uint4*)d_gh;   // 8 halves per uint4; node row = 8 uint4

    float4 f0 = make_float4(0.f, 0.f, 0.f, 0.f);
    float4 f1 = make_float4(0.f, 0.f, 0.f, 0.f);
    const __half2 hz = __float2half2_rn(0.f);

    int j = 0;
    for (; j + 16 <= cnt; j += 16) {
        int4 nb = __ldg((const int4*)&adj[j + 4 * s]);   // this substream's 4 nbrs
        uint4 v0 = __ldg(&gh4[(size_t)nb.x * 8 + c]);
        uint4 v1 = __ldg(&gh4[(size_t)nb.y * 8 + c]);
        uint4 v2 = __ldg(&gh4[(size_t)nb.z * 8 + c]);
        uint4 v3 = __ldg(&gh4[(size_t)nb.w * 8 + c]);
        // fp16 tree-add within the 4-neighbor group (depth 2, same as R9)
        __half2 a0 = __hadd2(__hadd2(u2h2(v0.x), u2h2(v1.x)),
                             __hadd2(u2h2(v2.x), u2h2(v3.x)));
        __half2 a1 = __hadd2(__hadd2(u2h2(v0.y), u2h2(v1.y)),
                             __hadd2(u2h2(v2.y), u2h2(v3.y)));
        __half2 a2 = __hadd2(__hadd2(u2h2(v0.z), u2h2(v1.z)),
                             __hadd2(u2h2(v2.z), u2h2(v3.z)));
        __half2 a3 = __hadd2(__hadd2(u2h2(v0.w), u2h2(v1.w)),
                             __hadd2(u2h2(v2.w), u2h2(v3.w)));
        float2 g0 = __half22float2(a0);
        float2 g1 = __half22float2(a1);
        float2 g2 = __half22float2(a2);
        float2 g3 = __half22float2(a3);
        f0.x += g0.x; f0.y += g0.y; f0.z += g1.x; f0.w += g1.y;
        f1.x += g2.x; f1.y += g2.y; f1.z += g3.x; f1.w += g3.y;
    }
    // tail: neighbors j..cnt-1, substream-strided (stride 4)
    {
        __half2 a0 = hz, a1 = hz, a2 = hz, a3 = hz;
        for (int t = j + s; t < cnt; t += 4) {
            int nb = __ldg(&adj[t]);
            uint4 v = __ldg(&gh4[(size_t)nb * 8 + c]);
            a0 = __hadd2(a0, u2h2(v.x));
            a1 = __hadd2(a1, u2h2(v.y));
            a2 = __hadd2(a2, u2h2(v.z));
            a3 = __hadd2(a3, u2h2(v.w));
        }
        float2 g0 = __half22float2(a0);
        float2 g1 = __half22float2(a1);
        float2 g2 = __half22float2(a2);
        float2 g3 = __half22float2(a3);
        f0.x += g0.x; f0.y += g0.y; f0.z += g1.x; f0.w += g1.y;
        f1.x += g2.x; f1.y += g2.y; f1.z += g3.x; f1.w += g3.y;
    }
    // combine the 4 substreams (lanes with same c, s=0..3)
#pragma unroll
    for (int d = 8; d <= 16; d <<= 1) {
        f0.x += __shfl_xor_sync(0xffffffffu, f0.x, d);
        f0.y += __shfl_xor_sync(0xffffffffu, f0.y, d);
        f0.z += __shfl_xor_sync(0xffffffffu, f0.z, d);
        f0.w += __shfl_xor_sync(0xffffffffu, f0.w, d);
        f1.x += __shfl_xor_sync(0xffffffffu, f1.x, d);
        f1.y += __shfl_xor_sync(0xffffffffu, f1.y, d);
        f1.z += __shfl_xor_sync(0xffffffffu, f1.z, d);
        f1.w += __shfl_xor_sync(0xffffffffu, f1.w, d);
    }
    if (s == 0) {
        float4* S4 = (float4*)d_S;        // node row = 16 float4
        S4[(size_t)node * 16 + 2 * c]     = f0;
        S4[(size_t)node * 16 + 2 * c + 1] = f1;
    }
}

// ==================================================================
// Tiled GEMM machinery: 128-node x 64-col tile, 256 threads,
// thread = 8 nodes (4 node-pairs) x 4 cols, FFMA2 inner product.
// ==================================================================
#define MT 128
#define KC 32
#define AS_PITCH 132
#define HS_PITCH 68

__device__ __forceinline__ void load_w_chunk(float* sWs, const float* W, int kc, int tid) {
#pragma unroll
    for (int l = 0; l < (KC * HDIM / 4) / 256; l++) {
        int idx = tid + l * 256;
        int k = idx >> 4, c4 = idx & 15;
        *(float4*)&sWs[k * HDIM + 4 * c4] =
            __ldg((const float4*)(W + (size_t)(kc + k) * HDIM + 4 * c4));
    }
}

template<int KP, bool SCALE_IN>
__device__ __forceinline__ void load_a_chunk(float* sAs, const float* in,
                                             int m0, int kc, int tid, int nn) {
#pragma unroll
    for (int l = 0; l < (MT * (KC / 4)) / 256; l++) {
        int idx = tid + l * 256;
        int node = idx >> 3, kq = idx & 7;
        int gm = m0 + node;
        float4 av = make_float4(0.f, 0.f, 0.f, 0.f);
        if (gm < nn) {
            av = __ldg((const float4*)(in + (size_t)gm * KP + kc + 4 * kq));
            if (SCALE_IN) {
                float dv = d_dinv[gm];
                av.x *= dv; av.y *= dv; av.z *= dv; av.w *= dv;
            }
        }
        sAs[(4 * kq + 0) * AS_PITCH + node] = av.x;
        sAs[(4 * kq + 1) * AS_PITCH + node] = av.y;
        sAs[(4 * kq + 2) * AS_PITCH + node] = av.z;
        sAs[(4 * kq + 3) * AS_PITCH + node] = av.w;
    }
}

__device__ __forceinline__ void mma_chunk(ull acc[4][4], const float* sAs,
                                          const float* sWs, int tx, int ty) {
#pragma unroll
    for (int k = 0; k < KC; k++) {
        ulonglong2 a01 = *(const ulonglong2*)&sAs[k * AS_PITCH + 8 * ty];
        ulonglong2 a23 = *(const ulonglong2*)&sAs[k * AS_PITCH + 8 * ty + 4];
        float4 wv = *(const float4*)&sWs[k * HDIM + 4 * tx];
        ull w0 = dup2(wv.x), w1 = dup2(wv.y), w2 = dup2(wv.z), w3 = dup2(wv.w);
        fma2(acc[0][0], a01.x, w0); fma2(acc[0][1], a01.x, w1);
        fma2(acc[0][2], a01.x, w2); fma2(acc[0][3], a01.x, w3);
        fma2(acc[1][0], a01.y, w0); fma2(acc[1][1], a01.y, w1);
        fma2(acc[1][2], a01.y, w2); fma2(acc[1][3], a01.y, w3);
        fma2(acc[2][0], a23.x, w0); fma2(acc[2][1], a23.x, w1);
        fma2(acc[2][2], a23.x, w2); fma2(acc[2][3], a23.x, w3);
        fma2(acc[3][0], a23.y, w0); fma2(acc[3][1], a23.y, w1);
        fma2(acc[3][2], a23.y, w2); fma2(acc[3][3], a23.y, w3);
    }
}

// store a relu+scale'd float4 (4 cols at 4*tx) into d_gh as 2 half2 (one STG.64)
__device__ __forceinline__ void store_g_half(int gm, int tx, float4 r) {
    __half2 h0 = __floats2half2_rn(r.x, r.y);
    __half2 h1 = __floats2half2_rn(r.z, r.w);
    uint2 pk;
    pk.x = *(unsigned int*)&h0;
    pk.y = *(unsigned int*)&h1;
    *(uint2*)&d_gh[(size_t)gm * 32 + 2 * tx] = pk;
}

// ------------------------------------------------------------------
// gemmA (fused): h = x@W_in+b_in (SMEM); g = dinv*relu(h@W1+b1) -> d_gh (fp16)
// also computes + stores dinv from d_cnt.
// ------------------------------------------------------------------
__global__ __launch_bounds__(256)
void gemm_fused_A(const float* __restrict__ x,
                  const float* __restrict__ W_in, const float* __restrict__ b_in,
                  const float* __restrict__ W1,   const float* __restrict__ b1,
                  int nn) {
    __shared__ __align__(16) float sU[MT * HS_PITCH];
    __shared__ __align__(16) float sW2[KC * HDIM];
    float* As = sU;
    float* Ws = sU + KC * AS_PITCH;
    float* Hs = sU;

    int tid = threadIdx.x;
    int tx = tid & 15, ty = tid >> 4;
    int m0 = blockIdx.x * MT;

    // phase 1: h = x @ W_in + b_in
    ull acc[4][4];
    {
        float4 b4 = __ldg((const float4*)(b_in + 4 * tx));
#pragma unroll
        for (int p = 0; p < 4; p++) {
            acc[p][0] = dup2(b4.x); acc[p][1] = dup2(b4.y);
            acc[p][2] = dup2(b4.z); acc[p][3] = dup2(b4.w);
        }
    }
#pragma unroll
    for (int kc = 0; kc < 128; kc += KC) {
        __syncthreads();
        load_w_chunk(Ws, W_in, kc, tid);
        load_a_chunk<128, false>(As, x, m0, kc, tid, nn);
        __syncthreads();
        mma_chunk(acc, As, Ws, tx, ty);
    }
    __syncthreads();
#pragma unroll
    for (int p = 0; p < 4; p++) {
        float4 re, ro;
        unpack2(acc[p][0], re.x, ro.x);
        unpack2(acc[p][1], re.y, ro.y);
        unpack2(acc[p][2], re.z, ro.z);
        unpack2(acc[p][3], re.w, ro.w);
        *(float4*)&Hs[(8 * ty + 2 * p)     * HS_PITCH + 4 * tx] = re;
        *(float4*)&Hs[(8 * ty + 2 * p + 1) * HS_PITCH + 4 * tx] = ro;
    }
    __syncthreads();

    // phase 2: g = dinv * relu(h @ W1 + b1)
    ull acc2[8][2];
    {
        float4 b4 = __ldg((const float4*)(b1 + 4 * tx));
#pragma unroll
        for (int n = 0; n < 8; n++) {
            acc2[n][0] = pack2(b4.x, b4.y);
            acc2[n][1] = pack2(b4.z, b4.w);
        }
    }
#pragma unroll
    for (int kc = 0; kc < HDIM; kc += KC) {
        __syncthreads();
        load_w_chunk(sW2, W1, kc, tid);
        __syncthreads();
#pragma unroll
        for (int k = 0; k < KC; k++) {
            ulonglong2 wp = *(const ulonglong2*)&sW2[k * HDIM + 4 * tx];
#pragma unroll
            for (int n = 0; n < 8; n++) {
                ull ad = dup2(Hs[(8 * ty + n) * HS_PITCH + kc + k]);
                fma2(acc2[n][0], ad, wp.x);
                fma2(acc2[n][1], ad, wp.y);
            }
        }
    }

    // epilogue: dinv from counts, relu, scale, store g (fp16)
#pragma unroll
    for (int n = 0; n < 8; n++) {
        int gm = m0 + 8 * ty + n;
        if (gm < nn) {
            int c = d_cnt[gm];
            float dv = c > 0 ? rsqrtf((float)c) : 0.0f;
            if (tx == 0) d_dinv[gm] = dv;
            float4 r;
            unpack2(acc2[n][0], r.x, r.y);
            unpack2(acc2[n][1], r.z, r.w);
            r.x = fmaxf(r.x, 0.f) * dv; r.y = fmaxf(r.y, 0.f) * dv;
            r.z = fmaxf(r.z, 0.f) * dv; r.w = fmaxf(r.w, 0.f) * dv;
            store_g_half(gm, tx, r);
        }
    }
}

// ------------------------------------------------------------------
// single tiled GEMM (K=64): out = f((maybe dinv*in) @ W + b)
// OUT_DST==BUF_S -> writes d_gh (fp16); BUF_EXT -> fp32 external out
// ------------------------------------------------------------------
template<int IN_SRC, int OUT_DST, bool SCALE_IN, bool RELU, bool SCALE_OUT>
__global__ __launch_bounds__(256)
void gemm_tiled(const float* __restrict__ ext_in, float* __restrict__ ext_out,
                const float* __restrict__ W, const float* __restrict__ bias, int nn) {
    __shared__ __align__(16) float As[KC * AS_PITCH];
    __shared__ __align__(16) float Ws[KC * HDIM];

    int tid = threadIdx.x;
    int tx = tid & 15, ty = tid >> 4;
    int m0 = blockIdx.x * MT;

    const float* in = (IN_SRC == BUF_EXT) ? ext_in : d_S;

    ull acc[4][4];
    {
        float4 b4 = __ldg((const float4*)(bias + 4 * tx));
#pragma unroll
        for (int p = 0; p < 4; p++) {
            acc[p][0] = dup2(b4.x); acc[p][1] = dup2(b4.y);
            acc[p][2] = dup2(b4.z); acc[p][3] = dup2(b4.w);
        }
    }
#pragma unroll
    for (int kc = 0; kc < HDIM; kc += KC) {
        __syncthreads();
        load_w_chunk(Ws, W, kc, tid);
        load_a_chunk<HDIM, SCALE_IN>(As, in, m0, kc, tid, nn);
        __syncthreads();
        mma_chunk(acc, As, Ws, tx, ty);
    }

#pragma unroll
    for (int p = 0; p < 4; p++) {
        float4 re, ro;
        unpack2(acc[p][0], re.x, ro.x);
        unpack2(acc[p][1], re.y, ro.y);
        unpack2(acc[p][2], re.z, ro.z);
        unpack2(acc[p][3], re.w, ro.w);
        int ge = m0 + 8 * ty + 2 * p;
        int go = ge + 1;
        if (RELU) {
            re.x = fmaxf(re.x, 0.f); re.y = fmaxf(re.y, 0.f);
            re.z = fmaxf(re.z, 0.f); re.w = fmaxf(re.w, 0.f);
            ro.x = fmaxf(ro.x, 0.f); ro.y = fmaxf(ro.y, 0.f);
            ro.z = fmaxf(ro.z, 0.f); ro.w = fmaxf(ro.w, 0.f);
        }
        if (ge < nn) {
            if (SCALE_OUT) {
                float dv = d_dinv[ge];
                re.x *= dv; re.y *= dv; re.z *= dv; re.w *= dv;
            }
            if (OUT_DST == BUF_S) store_g_half(ge, tx, re);
            else *(float4*)&ext_out[(size_t)ge * HDIM + 4 * tx] = re;
        }
        if (go < nn) {
            if (SCALE_OUT) {
                float dv = d_dinv[go];
                ro.x *= dv; ro.y *= dv; ro.z *= dv; ro.w *= dv;
            }
            if (OUT_DST == BUF_S) store_g_half(go, tx, ro);
            else *(float4*)&ext_out[(size_t)go * HDIM + 4 * tx] = ro;
        }
    }
}

// ------------------------------------------------------------------
// launch:  0 zero  1 fill  2 gemmA  3 gather1(profiled)  4 gemmB  5 gather2  6 gemmC
// ------------------------------------------------------------------
extern "C" void kernel_launch(void* const* d_in, const int* in_sizes, int n_in,
                              void* d_out, int out_size) {
    const float* x     = (const float*)d_in[0];
    const int*   ei    = (const int*)d_in[1];     // int32 edge indices
    const float* W_in  = (const float*)d_in[2];
    const float* b_in  = (const float*)d_in[3];
    const float* W1    = (const float*)d_in[4];
    const float* b1    = (const float*)d_in[5];
    const float* W2    = (const float*)d_in[6];
    const float* b2    = (const float*)d_in[7];
    const float* W_out = (const float*)d_in[8];
    const float* b_out = (const float*)d_in[9];
    float* out = (float*)d_out;

    int N = in_sizes[0] / 128;   // 100000
    int E = in_sizes[1] / 2;     // 1600000
    const int* e0 = ei;
    const int* e1 = ei + E;

    int tileBlocks = (N + MT - 1) / MT;
    int gatherBlocks = (N + 7) / 8;

    zero_cnt_kernel<<<(N + 255) / 256, 256>>>(N);
    fill_adj_kernel<<<(E + 255) / 256, 256>>>(e0, e1, E);

    // fused: h = x@W_in+b_in; g = dinv*relu(h@W1+b1) -> fp16; dinv
    gemm_fused_A<<<tileBlocks, 256>>>(x, W_in, b_in, W1, b1, N);

    // propagate 1  (profiled slot)
    gather_kernel<<<gatherBlocks, 256>>>(N);

    // g = dinv * relu((dinv*S)@W2 + b2) -> d_gh (fp16)
    gemm_tiled<BUF_S, BUF_S, true, true, true>
        <<<tileBlocks, 256>>>(nullptr, nullptr, W2, b2, N);

    // propagate 2
    gather_kernel<<<gatherBlocks, 256>>>(N);

    // out = (dinv*S) @ W_out + b_out  (fp32)
    gemm_tiled<BUF_S, BUF_EXT, true, false, false>
        <<<tileBlocks, 256>>>(nullptr, out, W_out, b_out, N);
}

// round 11
// speedup vs baseline: 1.0933x; 1.0933x over previous
#include <cuda_runtime.h>
#include <cuda_fp16.h>

#define NMAX 100000
#define HDIM 64
#define SLOTS 128     // max degree safety: Poisson(32) max over 100k nodes ~58

// ---- device scratch (no allocations allowed), 16B-aligned ----
__device__ __align__(16) int     d_cnt [NMAX];
__device__ __align__(16) int     d_adj [(size_t)NMAX * SLOTS];  // padded adjacency
__device__ __align__(16) float   d_dinv[NMAX];
__device__ __align__(16) __half2 d_gh[(size_t)NMAX * (HDIM / 2)]; // gather source, fp16 (dinv-folded)
__device__ __align__(16) float   d_S [(size_t)NMAX * HDIM];     // propagate result (fp32)

#define BUF_EXT 0
#define BUF_S   1

// ---- packed f32x2 helpers (Blackwell FFMA2 via PTX) ----
typedef unsigned long long ull;
__device__ __forceinline__ ull pack2(float lo, float hi) {
    ull r; asm("mov.b64 %0, {%1, %2};" : "=l"(r) : "f"(lo), "f"(hi)); return r;
}
__device__ __forceinline__ ull dup2(float v) {
    ull r; asm("mov.b64 %0, {%1, %1};" : "=l"(r) : "f"(v)); return r;
}
__device__ __forceinline__ void unpack2(ull v, float& lo, float& hi) {
    asm("mov.b64 {%0, %1}, %2;" : "=f"(lo), "=f"(hi) : "l"(v));
}
__device__ __forceinline__ void fma2(ull& d, ull a, ull b) {
    asm("fma.rn.f32x2 %0, %1, %2, %3;" : "=l"(d) : "l"(a), "l"(b), "l"(d));
}
__device__ __forceinline__ __half2 u2h2(unsigned int u) {
    __half2 h; *(unsigned int*)&h = u; return h;
}

// ------------------------------------------------------------------
// adjacency build (edge_index is int32: JAX x64 disabled)
// ------------------------------------------------------------------
__global__ void zero_cnt_kernel(int n) {
    int i = blockIdx.x * blockDim.x + threadIdx.x;
    if (i < n) d_cnt[i] = 0;
}

__global__ void fill_adj_kernel(const int* __restrict__ e0,
                                const int* __restrict__ e1, int E) {
    int e = blockIdx.x * blockDim.x + threadIdx.x;
    if (e >= E) return;
    int u = __ldg(&e0[e]);
    int v = __ldg(&e1[e]);
    int pu = atomicAdd(&d_cnt[u], 1);
    if (pu < SLOTS) d_adj[(size_t)u * SLOTS + pu] = v;
    int pv = atomicAdd(&d_cnt[v], 1);
    if (pv < SLOTS) d_adj[(size_t)v * SLOTS + pv] = u;
}

// ------------------------------------------------------------------
// propagate (gather-only): S[i] = sum_{j in adj[i]} g[j]
// warp per node; half-warp w owns a neighbor substream; lane covers 4 cols
// (LDG.64); fp16 group accumulation (<=8 nbrs) + fp32 flush.
// Index int4 for the NEXT group is prefetched before the current group's
// data loads, removing the idx-load latency from the dependent chain.
// ------------------------------------------------------------------
__global__ __launch_bounds__(256)
void gather_kernel(int nn) {
    int node = blockIdx.x * 8 + (threadIdx.x >> 5);
    int lane = threadIdx.x & 31;
    if (node >= nn) return;
    int w = lane >> 4;         // half-warp id (neighbor substream)
    int c = lane & 15;         // column quad: cols 4c..4c+3
    int cnt = min(d_cnt[node], SLOTS);
    const int* adj = &d_adj[(size_t)node * SLOTS];
    const uint2* gh2 = (const uint2*)d_gh;   // 4 halves per uint2; node row = 16 uint2

    float4 facc = make_float4(0.f, 0.f, 0.f, 0.f);
    const __half2 hz = __float2half2_rn(0.f);

    int j = 0;
    int4 nb = make_int4(0, 0, 0, 0);
    if (8 <= cnt) nb = __ldg((const int4*)&adj[4 * w]);
    for (; j + 8 <= cnt; j += 8) {
        int4 cur = nb;
        if (j + 16 <= cnt)                               // prefetch next group
            nb = __ldg((const int4*)&adj[j + 8 + 4 * w]);
        uint2 v0 = __ldg(&gh2[(size_t)cur.x * 16 + c]);
        uint2 v1 = __ldg(&gh2[(size_t)cur.y * 16 + c]);
        uint2 v2 = __ldg(&gh2[(size_t)cur.z * 16 + c]);
        uint2 v3 = __ldg(&gh2[(size_t)cur.w * 16 + c]);
        __half2 h0 = __hadd2(__hadd2(u2h2(v0.x), u2h2(v1.x)),
                             __hadd2(u2h2(v2.x), u2h2(v3.x)));
        __half2 h1 = __hadd2(__hadd2(u2h2(v0.y), u2h2(v1.y)),
                             __hadd2(u2h2(v2.y), u2h2(v3.y)));
        float2 f0 = __half22float2(h0);
        float2 f1 = __half22float2(h1);
        facc.x += f0.x; facc.y += f0.y; facc.z += f1.x; facc.w += f1.y;
    }
    // tail: neighbors j..cnt-1, interleaved by half-warp (stride 2)
    {
        __half2 h0 = hz, h1 = hz;
        for (int t = j + w; t < cnt; t += 2) {
            int nb1 = __ldg(&adj[t]);
            uint2 v = __ldg(&gh2[(size_t)nb1 * 16 + c]);
            h0 = __hadd2(h0, u2h2(v.x));
            h1 = __hadd2(h1, u2h2(v.y));
        }
        float2 f0 = __half22float2(h0);
        float2 f1 = __half22float2(h1);
        facc.x += f0.x; facc.y += f0.y; facc.z += f1.x; facc.w += f1.y;
    }
    // combine the two half-warp substreams (lanes c and c+16 hold same cols)
    facc.x += __shfl_xor_sync(0xffffffffu, facc.x, 16);
    facc.y += __shfl_xor_sync(0xffffffffu, facc.y, 16);
    facc.z += __shfl_xor_sync(0xffffffffu, facc.z, 16);
    facc.w += __shfl_xor_sync(0xffffffffu, facc.w, 16);
    if (w == 0)
        ((float4*)d_S)[(size_t)node * 16 + c] = facc;   // overwrite, no zeroing
}

// ==================================================================
// Tiled GEMM machinery: 128-node x 64-col tile, 256 threads,
// thread = 8 nodes (4 node-pairs) x 4 cols, FFMA2 inner product.
// ==================================================================
#define MT 128
#define KC 32
#define AS_PITCH 132
#define HS_PITCH 68

__device__ __forceinline__ void load_w_chunk(float* sWs, const float* W, int kc, int tid) {
#pragma unroll
    for (int l = 0; l < (KC * HDIM / 4) / 256; l++) {
        int idx = tid + l * 256;
        int k = idx >> 4, c4 = idx & 15;
        *(float4*)&sWs[k * HDIM + 4 * c4] =
            __ldg((const float4*)(W + (size_t)(kc + k) * HDIM + 4 * c4));
    }
}

template<int KP, bool SCALE_IN>
__device__ __forceinline__ void load_a_chunk(float* sAs, const float* in,
                                             int m0, int kc, int tid, int nn) {
#pragma unroll
    for (int l = 0; l < (MT * (KC / 4)) / 256; l++) {
        int idx = tid + l * 256;
        int node = idx >> 3, kq = idx & 7;
        int gm = m0 + node;
        float4 av = make_float4(0.f, 0.f, 0.f, 0.f);
        if (gm < nn) {
            av = __ldg((const float4*)(in + (size_t)gm * KP + kc + 4 * kq));
            if (SCALE_IN) {
                float dv = d_dinv[gm];
                av.x *= dv; av.y *= dv; av.z *= dv; av.w *= dv;
            }
        }
        sAs[(4 * kq + 0) * AS_PITCH + node] = av.x;
        sAs[(4 * kq + 1) * AS_PITCH + node] = av.y;
        sAs[(4 * kq + 2) * AS_PITCH + node] = av.z;
        sAs[(4 * kq + 3) * AS_PITCH + node] = av.w;
    }
}

__device__ __forceinline__ void mma_chunk(ull acc[4][4], const float* sAs,
                                          const float* sWs, int tx, int ty) {
#pragma unroll
    for (int k = 0; k < KC; k++) {
        ulonglong2 a01 = *(const ulonglong2*)&sAs[k * AS_PITCH + 8 * ty];
        ulonglong2 a23 = *(const ulonglong2*)&sAs[k * AS_PITCH + 8 * ty + 4];
        float4 wv = *(const float4*)&sWs[k * HDIM + 4 * tx];
        ull w0 = dup2(wv.x), w1 = dup2(wv.y), w2 = dup2(wv.z), w3 = dup2(wv.w);
        fma2(acc[0][0], a01.x, w0); fma2(acc[0][1], a01.x, w1);
        fma2(acc[0][2], a01.x, w2); fma2(acc[0][3], a01.x, w3);
        fma2(acc[1][0], a01.y, w0); fma2(acc[1][1], a01.y, w1);
        fma2(acc[1][2], a01.y, w2); fma2(acc[1][3], a01.y, w3);
        fma2(acc[2][0], a23.x, w0); fma2(acc[2][1], a23.x, w1);
        fma2(acc[2][2], a23.x, w2); fma2(acc[2][3], a23.x, w3);
        fma2(acc[3][0], a23.y, w0); fma2(acc[3][1], a23.y, w1);
        fma2(acc[3][2], a23.y, w2); fma2(acc[3][3], a23.y, w3);
    }
}

// store a relu+scale'd float4 (4 cols at 4*tx) into d_gh as 2 half2 (one STG.64)
__device__ __forceinline__ void store_g_half(int gm, int tx, float4 r) {
    __half2 h0 = __floats2half2_rn(r.x, r.y);
    __half2 h1 = __floats2half2_rn(r.z, r.w);
    uint2 pk;
    pk.x = *(unsigned int*)&h0;
    pk.y = *(unsigned int*)&h1;
    *(uint2*)&d_gh[(size_t)gm * 32 + 2 * tx] = pk;
}

// ------------------------------------------------------------------
// gemmA (fused): h = x@W_in+b_in (SMEM); g = dinv*relu(h@W1+b1) -> d_gh (fp16)
// also computes + stores dinv from d_cnt.
// ------------------------------------------------------------------
__global__ __launch_bounds__(256)
void gemm_fused_A(const float* __restrict__ x,
                  const float* __restrict__ W_in, const float* __restrict__ b_in,
                  const float* __restrict__ W1,   const float* __restrict__ b1,
                  int nn) {
    __shared__ __align__(16) float sU[MT * HS_PITCH];
    __shared__ __align__(16) float sW2[KC * HDIM];
    float* As = sU;
    float* Ws = sU + KC * AS_PITCH;
    float* Hs = sU;

    int tid = threadIdx.x;
    int tx = tid & 15, ty = tid >> 4;
    int m0 = blockIdx.x * MT;

    // phase 1: h = x @ W_in + b_in
    ull acc[4][4];
    {
        float4 b4 = __ldg((const float4*)(b_in + 4 * tx));
#pragma unroll
        for (int p = 0; p < 4; p++) {
            acc[p][0] = dup2(b4.x); acc[p][1] = dup2(b4.y);
            acc[p][2] = dup2(b4.z); acc[p][3] = dup2(b4.w);
        }
    }
#pragma unroll
    for (int kc = 0; kc < 128; kc += KC) {
        __syncthreads();
        load_w_chunk(Ws, W_in, kc, tid);
        load_a_chunk<128, false>(As, x, m0, kc, tid, nn);
        __syncthreads();
        mma_chunk(acc, As, Ws, tx, ty);
    }
    __syncthreads();
#pragma unroll
    for (int p = 0; p < 4; p++) {
        float4 re, ro;
        unpack2(acc[p][0], re.x, ro.x);
        unpack2(acc[p][1], re.y, ro.y);
        unpack2(acc[p][2], re.z, ro.z);
        unpack2(acc[p][3], re.w, ro.w);
        *(float4*)&Hs[(8 * ty + 2 * p)     * HS_PITCH + 4 * tx] = re;
        *(float4*)&Hs[(8 * ty + 2 * p + 1) * HS_PITCH + 4 * tx] = ro;
    }
    __syncthreads();

    // phase 2: g = dinv * relu(h @ W1 + b1)
    ull acc2[8][2];
    {
        float4 b4 = __ldg((const float4*)(b1 + 4 * tx));
#pragma unroll
        for (int n = 0; n < 8; n++) {
            acc2[n][0] = pack2(b4.x, b4.y);
            acc2[n][1] = pack2(b4.z, b4.w);
        }
    }
#pragma unroll
    for (int kc = 0; kc < HDIM; kc += KC) {
        __syncthreads();
        load_w_chunk(sW2, W1, kc, tid);
        __syncthreads();
#pragma unroll
        for (int k = 0; k < KC; k++) {
            ulonglong2 wp = *(const ulonglong2*)&sW2[k * HDIM + 4 * tx];
#pragma unroll
            for (int n = 0; n < 8; n++) {
                ull ad = dup2(Hs[(8 * ty + n) * HS_PITCH + kc + k]);
                fma2(acc2[n][0], ad, wp.x);
                fma2(acc2[n][1], ad, wp.y);
            }
        }
    }

    // epilogue: dinv from counts, relu, scale, store g (fp16)
#pragma unroll
    for (int n = 0; n < 8; n++) {
        int gm = m0 + 8 * ty + n;
        if (gm < nn) {
            int c = d_cnt[gm];
            float dv = c > 0 ? rsqrtf((float)c) : 0.0f;
            if (tx == 0) d_dinv[gm] = dv;
            float4 r;
            unpack2(acc2[n][0], r.x, r.y);
            unpack2(acc2[n][1], r.z, r.w);
            r.x = fmaxf(r.x, 0.f) * dv; r.y = fmaxf(r.y, 0.f) * dv;
            r.z = fmaxf(r.z, 0.f) * dv; r.w = fmaxf(r.w, 0.f) * dv;
            store_g_half(gm, tx, r);
        }
    }
}

// ------------------------------------------------------------------
// single tiled GEMM (K=64): out = f((maybe dinv*in) @ W + b)
// OUT_DST==BUF_S -> writes d_gh (fp16); BUF_EXT -> fp32 external out
// ------------------------------------------------------------------
template<int IN_SRC, int OUT_DST, bool SCALE_IN, bool RELU, bool SCALE_OUT>
__global__ __launch_bounds__(256)
void gemm_tiled(const float* __restrict__ ext_in, float* __restrict__ ext_out,
                const float* __restrict__ W, const float* __restrict__ bias, int nn) {
    __shared__ __align__(16) float As[KC * AS_PITCH];
    __shared__ __align__(16) float Ws[KC * HDIM];

    int tid = threadIdx.x;
    int tx = tid & 15, ty = tid >> 4;
    int m0 = blockIdx.x * MT;

    const float* in = (IN_SRC == BUF_EXT) ? ext_in : d_S;

    ull acc[4][4];
    {
        float4 b4 = __ldg((const float4*)(bias + 4 * tx));
#pragma unroll
        for (int p = 0; p < 4; p++) {
            acc[p][0] = dup2(b4.x); acc[p][1] = dup2(b4.y);
            acc[p][2] = dup2(b4.z); acc[p][3] = dup2(b4.w);
        }
    }
#pragma unroll
    for (int kc = 0; kc < HDIM; kc += KC) {
        __syncthreads();
        load_w_chunk(Ws, W, kc, tid);
        load_a_chunk<HDIM, SCALE_IN>(As, in, m0, kc, tid, nn);
        __syncthreads();
        mma_chunk(acc, As, Ws, tx, ty);
    }

#pragma unroll
    for (int p = 0; p < 4; p++) {
        float4 re, ro;
        unpack2(acc[p][0], re.x, ro.x);
        unpack2(acc[p][1], re.y, ro.y);
        unpack2(acc[p][2], re.z, ro.z);
        unpack2(acc[p][3], re.w, ro.w);
        int ge = m0 + 8 * ty + 2 * p;
        int go = ge + 1;
        if (RELU) {
            re.x = fmaxf(re.x, 0.f); re.y = fmaxf(re.y, 0.f);
            re.z = fmaxf(re.z, 0.f); re.w = fmaxf(re.w, 0.f);
            ro.x = fmaxf(ro.x, 0.f); ro.y = fmaxf(ro.y, 0.f);
            ro.z = fmaxf(ro.z, 0.f); ro.w = fmaxf(ro.w, 0.f);
        }
        if (ge < nn) {
            if (SCALE_OUT) {
                float dv = d_dinv[ge];
                re.x *= dv; re.y *= dv; re.z *= dv; re.w *= dv;
            }
            if (OUT_DST == BUF_S) store_g_half(ge, tx, re);
            else *(float4*)&ext_out[(size_t)ge * HDIM + 4 * tx] = re;
        }
        if (go < nn) {
            if (SCALE_OUT) {
                float dv = d_dinv[go];
                ro.x *= dv; ro.y *= dv; ro.z *= dv; ro.w *= dv;
            }
            if (OUT_DST == BUF_S) store_g_half(go, tx, ro);
            else *(float4*)&ext_out[(size_t)go * HDIM + 4 * tx] = ro;
        }
    }
}

// ------------------------------------------------------------------
// launch:  0 zero  1 fill  2 gemmA  3 gather1(profiled)  4 gemmB  5 gather2  6 gemmC
// ------------------------------------------------------------------
extern "C" void kernel_launch(void* const* d_in, const int* in_sizes, int n_in,
                              void* d_out, int out_size) {
    const float* x     = (const float*)d_in[0];
    const int*   ei    = (const int*)d_in[1];     // int32 edge indices
    const float* W_in  = (const float*)d_in[2];
    const float* b_in  = (const float*)d_in[3];
    const float* W1    = (const float*)d_in[4];
    const float* b1    = (const float*)d_in[5];
    const float* W2    = (const float*)d_in[6];
    const float* b2    = (const float*)d_in[7];
    const float* W_out = (const float*)d_in[8];
    const float* b_out = (const float*)d_in[9];
    float* out = (float*)d_out;

    int N = in_sizes[0] / 128;   // 100000
    int E = in_sizes[1] / 2;     // 1600000
    const int* e0 = ei;
    const int* e1 = ei + E;

    int tileBlocks = (N + MT - 1) / MT;
    int gatherBlocks = (N + 7) / 8;

    zero_cnt_kernel<<<(N + 255) / 256, 256>>>(N);
    fill_adj_kernel<<<(E + 255) / 256, 256>>>(e0, e1, E);

    // fused: h = x@W_in+b_in; g = dinv*relu(h@W1+b1) -> fp16; dinv
    gemm_fused_A<<<tileBlocks, 256>>>(x, W_in, b_in, W1, b1, N);

    // propagate 1  (profiled slot)
    gather_kernel<<<gatherBlocks, 256>>>(N);

    // g = dinv * relu((dinv*S)@W2 + b2) -> d_gh (fp16)
    gemm_tiled<BUF_S, BUF_S, true, true, true>
        <<<tileBlocks, 256>>>(nullptr, nullptr, W2, b2, N);

    // propagate 2
    gather_kernel<<<gatherBlocks, 256>>>(N);

    // out = (dinv*S) @ W_out + b_out  (fp32)
    gemm_tiled<BUF_S, BUF_EXT, true, false, false>
        <<<tileBlocks, 256>>>(nullptr, out, W_out, b_out, N);
}

// round 12
// speedup vs baseline: 1.1199x; 1.0244x over previous
#include <cuda_runtime.h>
#include <cuda_fp16.h>

#define NMAX 100000
#define HDIM 64
#define SLOTS 128     // max degree safety: Poisson(32) max over 100k nodes ~58

// ---- device scratch (no allocations allowed), 16B-aligned ----
__device__ __align__(16) int     d_cnt [NMAX];
__device__ __align__(16) int     d_adj [(size_t)NMAX * SLOTS];  // padded adjacency
__device__ __align__(16) float   d_dinv[NMAX];
// +1 row: dummy zero node (index NMAX) used for tail padding
__device__ __align__(16) __half2 d_gh[(size_t)(NMAX + 1) * (HDIM / 2)];
__device__ __align__(16) float   d_S [(size_t)NMAX * HDIM];     // propagate result (fp32)

#define BUF_EXT 0
#define BUF_S   1

// ---- packed f32x2 helpers (Blackwell FFMA2 via PTX) ----
typedef unsigned long long ull;
__device__ __forceinline__ ull pack2(float lo, float hi) {
    ull r; asm("mov.b64 %0, {%1, %2};" : "=l"(r) : "f"(lo), "f"(hi)); return r;
}
__device__ __forceinline__ ull dup2(float v) {
    ull r; asm("mov.b64 %0, {%1, %1};" : "=l"(r) : "f"(v)); return r;
}
__device__ __forceinline__ void unpack2(ull v, float& lo, float& hi) {
    asm("mov.b64 {%0, %1}, %2;" : "=f"(lo), "=f"(hi) : "l"(v));
}
__device__ __forceinline__ void fma2(ull& d, ull a, ull b) {
    asm("fma.rn.f32x2 %0, %1, %2, %3;" : "=l"(d) : "l"(a), "l"(b), "l"(d));
}
__device__ __forceinline__ __half2 u2h2(unsigned int u) {
    __half2 h; *(unsigned int*)&h = u; return h;
}

// ------------------------------------------------------------------
// adjacency build (edge_index is int32: JAX x64 disabled)
// ------------------------------------------------------------------
__global__ void zero_cnt_kernel(int n) {
    int i = blockIdx.x * blockDim.x + threadIdx.x;
    if (i < n) d_cnt[i] = 0;
    if (i < 32)   // zero the dummy gather row (row NMAX of d_gh)
        ((unsigned int*)&d_gh[(size_t)NMAX * 32])[i] = 0u;
}

__global__ void fill_adj_kernel(const int* __restrict__ e0,
                                const int* __restrict__ e1, int E) {
    int e = blockIdx.x * blockDim.x + threadIdx.x;
    if (e >= E) return;
    int u = __ldg(&e0[e]);
    int v = __ldg(&e1[e]);
    int pu = atomicAdd(&d_cnt[u], 1);
    if (pu < SLOTS) d_adj[(size_t)u * SLOTS + pu] = v;
    int pv = atomicAdd(&d_cnt[v], 1);
    if (pv < SLOTS) d_adj[(size_t)v * SLOTS + pv] = u;
}

// pad each adjacency list with dummy node NMAX up to a multiple of 8
__global__ void pad_adj_kernel(int nn) {
    int i = blockIdx.x * blockDim.x + threadIdx.x;
    if (i >= nn) return;
    int c = min(d_cnt[i], SLOTS);
    int r = min((c + 7) & ~7, SLOTS);
    for (int t = c; t < r; t++) d_adj[(size_t)i * SLOTS + t] = NMAX;
}

// ------------------------------------------------------------------
// propagate (gather-only): S[i] = sum_{j in adj[i]} g[j]
// warp per node; half-warp w owns a neighbor substream; lane covers 4 cols
// (LDG.64); fp16 group accumulation (8 nbrs) + fp32 flush. No tail:
// lists are padded to a multiple of 8 with a zero dummy row.
// Next group's index int4 is prefetched ahead of the data loads.
// ------------------------------------------------------------------
__global__ __launch_bounds__(256)
void gather_kernel(int nn) {
    int node = blockIdx.x * 8 + (threadIdx.x >> 5);
    int lane = threadIdx.x & 31;
    if (node >= nn) return;
    int w = lane >> 4;         // half-warp id (neighbor substream)
    int c = lane & 15;         // column quad: cols 4c..4c+3
    int cnt = min(d_cnt[node], SLOTS);
    int cntp = min((cnt + 7) & ~7, SLOTS);   // padded length (multiple of 8)
    const int* adj = &d_adj[(size_t)node * SLOTS];
    const uint2* gh2 = (const uint2*)d_gh;   // 4 halves per uint2; node row = 16 uint2

    float4 facc = make_float4(0.f, 0.f, 0.f, 0.f);

    int4 nb = make_int4(NMAX, NMAX, NMAX, NMAX);
    if (cntp > 0) nb = __ldg((const int4*)&adj[4 * w]);
    for (int j = 0; j < cntp; j += 8) {
        int4 cur = nb;
        if (j + 8 < cntp)                                // prefetch next group
            nb = __ldg((const int4*)&adj[j + 8 + 4 * w]);
        uint2 v0 = __ldg(&gh2[(size_t)cur.x * 16 + c]);
        uint2 v1 = __ldg(&gh2[(size_t)cur.y * 16 + c]);
        uint2 v2 = __ldg(&gh2[(size_t)cur.z * 16 + c]);
        uint2 v3 = __ldg(&gh2[(size_t)cur.w * 16 + c]);
        __half2 h0 = __hadd2(__hadd2(u2h2(v0.x), u2h2(v1.x)),
                             __hadd2(u2h2(v2.x), u2h2(v3.x)));
        __half2 h1 = __hadd2(__hadd2(u2h2(v0.y), u2h2(v1.y)),
                             __hadd2(u2h2(v2.y), u2h2(v3.y)));
        float2 f0 = __half22float2(h0);
        float2 f1 = __half22float2(h1);
        facc.x += f0.x; facc.y += f0.y; facc.z += f1.x; facc.w += f1.y;
    }
    // combine the two half-warp substreams (lanes c and c+16 hold same cols)
    facc.x += __shfl_xor_sync(0xffffffffu, facc.x, 16);
    facc.y += __shfl_xor_sync(0xffffffffu, facc.y, 16);
    facc.z += __shfl_xor_sync(0xffffffffu, facc.z, 16);
    facc.w += __shfl_xor_sync(0xffffffffu, facc.w, 16);
    if (w == 0)
        ((float4*)d_S)[(size_t)node * 16 + c] = facc;   // overwrite, no zeroing
}

// ==================================================================
// Tiled GEMM machinery: 128-node x 64-col tile, 256 threads,
// thread = 8 nodes (4 node-pairs) x 4 cols, FFMA2 inner product.
// ==================================================================
#define MT 128
#define KC 32
#define AS_PITCH 132
#define HS_PITCH 68

__device__ __forceinline__ void load_w_chunk(float* sWs, const float* W, int kc, int tid) {
#pragma unroll
    for (int l = 0; l < (KC * HDIM / 4) / 256; l++) {
        int idx = tid + l * 256;
        int k = idx >> 4, c4 = idx & 15;
        *(float4*)&sWs[k * HDIM + 4 * c4] =
            __ldg((const float4*)(W + (size_t)(kc + k) * HDIM + 4 * c4));
    }
}

template<int KP, bool SCALE_IN>
__device__ __forceinline__ void load_a_chunk(float* sAs, const float* in,
                                             int m0, int kc, int tid, int nn) {
#pragma unroll
    for (int l = 0; l < (MT * (KC / 4)) / 256; l++) {
        int idx = tid + l * 256;
        int node = idx >> 3, kq = idx & 7;
        int gm = m0 + node;
        float4 av = make_float4(0.f, 0.f, 0.f, 0.f);
        if (gm < nn) {
            av = __ldg((const float4*)(in + (size_t)gm * KP + kc + 4 * kq));
            if (SCALE_IN) {
                float dv = d_dinv[gm];
                av.x *= dv; av.y *= dv; av.z *= dv; av.w *= dv;
            }
        }
        sAs[(4 * kq + 0) * AS_PITCH + node] = av.x;
        sAs[(4 * kq + 1) * AS_PITCH + node] = av.y;
        sAs[(4 * kq + 2) * AS_PITCH + node] = av.z;
        sAs[(4 * kq + 3) * AS_PITCH + node] = av.w;
    }
}

__device__ __forceinline__ void mma_chunk(ull acc[4][4], const float* sAs,
                                          const float* sWs, int tx, int ty) {
#pragma unroll
    for (int k = 0; k < KC; k++) {
        ulonglong2 a01 = *(const ulonglong2*)&sAs[k * AS_PITCH + 8 * ty];
        ulonglong2 a23 = *(const ulonglong2*)&sAs[k * AS_PITCH + 8 * ty + 4];
        float4 wv = *(const float4*)&sWs[k * HDIM + 4 * tx];
        ull w0 = dup2(wv.x), w1 = dup2(wv.y), w2 = dup2(wv.z), w3 = dup2(wv.w);
        fma2(acc[0][0], a01.x, w0); fma2(acc[0][1], a01.x, w1);
        fma2(acc[0][2], a01.x, w2); fma2(acc[0][3], a01.x, w3);
        fma2(acc[1][0], a01.y, w0); fma2(acc[1][1], a01.y, w1);
        fma2(acc[1][2], a01.y, w2); fma2(acc[1][3], a01.y, w3);
        fma2(acc[2][0], a23.x, w0); fma2(acc[2][1], a23.x, w1);
        fma2(acc[2][2], a23.x, w2); fma2(acc[2][3], a23.x, w3);
        fma2(acc[3][0], a23.y, w0); fma2(acc[3][1], a23.y, w1);
        fma2(acc[3][2], a23.y, w2); fma2(acc[3][3], a23.y, w3);
    }
}

// store a relu+scale'd float4 (4 cols at 4*tx) into d_gh as 2 half2 (one STG.64)
__device__ __forceinline__ void store_g_half(int gm, int tx, float4 r) {
    __half2 h0 = __floats2half2_rn(r.x, r.y);
    __half2 h1 = __floats2half2_rn(r.z, r.w);
    uint2 pk;
    pk.x = *(unsigned int*)&h0;
    pk.y = *(unsigned int*)&h1;
    *(uint2*)&d_gh[(size_t)gm * 32 + 2 * tx] = pk;
}

// ------------------------------------------------------------------
// gemmA (fused): h = x@W_in+b_in (SMEM); g = dinv*relu(h@W1+b1) -> d_gh (fp16)
// also computes + stores dinv from d_cnt.
// ------------------------------------------------------------------
__global__ __launch_bounds__(256)
void gemm_fused_A(const float* __restrict__ x,
                  const float* __restrict__ W_in, const float* __restrict__ b_in,
                  const float* __restrict__ W1,   const float* __restrict__ b1,
                  int nn) {
    __shared__ __align__(16) float sU[MT * HS_PITCH];
    __shared__ __align__(16) float sW2[KC * HDIM];
    float* As = sU;
    float* Ws = sU + KC * AS_PITCH;
    float* Hs = sU;

    int tid = threadIdx.x;
    int tx = tid & 15, ty = tid >> 4;
    int m0 = blockIdx.x * MT;

    // phase 1: h = x @ W_in + b_in
    ull acc[4][4];
    {
        float4 b4 = __ldg((const float4*)(b_in + 4 * tx));
#pragma unroll
        for (int p = 0; p < 4; p++) {
            acc[p][0] = dup2(b4.x); acc[p][1] = dup2(b4.y);
            acc[p][2] = dup2(b4.z); acc[p][3] = dup2(b4.w);
        }
    }
#pragma unroll
    for (int kc = 0; kc < 128; kc += KC) {
        __syncthreads();
        load_w_chunk(Ws, W_in, kc, tid);
        load_a_chunk<128, false>(As, x, m0, kc, tid, nn);
        __syncthreads();
        mma_chunk(acc, As, Ws, tx, ty);
    }
    __syncthreads();
#pragma unroll
    for (int p = 0; p < 4; p++) {
        float4 re, ro;
        unpack2(acc[p][0], re.x, ro.x);
        unpack2(acc[p][1], re.y, ro.y);
        unpack2(acc[p][2], re.z, ro.z);
        unpack2(acc[p][3], re.w, ro.w);
        *(float4*)&Hs[(8 * ty + 2 * p)     * HS_PITCH + 4 * tx] = re;
        *(float4*)&Hs[(8 * ty + 2 * p + 1) * HS_PITCH + 4 * tx] = ro;
    }
    __syncthreads();

    // phase 2: g = dinv * relu(h @ W1 + b1)
    ull acc2[8][2];
    {
        float4 b4 = __ldg((const float4*)(b1 + 4 * tx));
#pragma unroll
        for (int n = 0; n < 8; n++) {
            acc2[n][0] = pack2(b4.x, b4.y);
            acc2[n][1] = pack2(b4.z, b4.w);
        }
    }
#pragma unroll
    for (int kc = 0; kc < HDIM; kc += KC) {
        __syncthreads();
        load_w_chunk(sW2, W1, kc, tid);
        __syncthreads();
#pragma unroll
        for (int k = 0; k < KC; k++) {
            ulonglong2 wp = *(const ulonglong2*)&sW2[k * HDIM + 4 * tx];
#pragma unroll
            for (int n = 0; n < 8; n++) {
                ull ad = dup2(Hs[(8 * ty + n) * HS_PITCH + kc + k]);
                fma2(acc2[n][0], ad, wp.x);
                fma2(acc2[n][1], ad, wp.y);
            }
        }
    }

    // epilogue: dinv from counts, relu, scale, store g (fp16)
#pragma unroll
    for (int n = 0; n < 8; n++) {
        int gm = m0 + 8 * ty + n;
        if (gm < nn) {
            int c = d_cnt[gm];
            float dv = c > 0 ? rsqrtf((float)c) : 0.0f;
            if (tx == 0) d_dinv[gm] = dv;
            float4 r;
            unpack2(acc2[n][0], r.x, r.y);
            unpack2(acc2[n][1], r.z, r.w);
            r.x = fmaxf(r.x, 0.f) * dv; r.y = fmaxf(r.y, 0.f) * dv;
            r.z = fmaxf(r.z, 0.f) * dv; r.w = fmaxf(r.w, 0.f) * dv;
            store_g_half(gm, tx, r);
        }
    }
}

// ------------------------------------------------------------------
// single tiled GEMM (K=64): out = f((maybe dinv*in) @ W + b)
// OUT_DST==BUF_S -> writes d_gh (fp16); BUF_EXT -> fp32 external out
// ------------------------------------------------------------------
template<int IN_SRC, int OUT_DST, bool SCALE_IN, bool RELU, bool SCALE_OUT>
__global__ __launch_bounds__(256)
void gemm_tiled(const float* __restrict__ ext_in, float* __restrict__ ext_out,
                const float* __restrict__ W, const float* __restrict__ bias, int nn) {
    __shared__ __align__(16) float As[KC * AS_PITCH];
    __shared__ __align__(16) float Ws[KC * HDIM];

    int tid = threadIdx.x;
    int tx = tid & 15, ty = tid >> 4;
    int m0 = blockIdx.x * MT;

    const float* in = (IN_SRC == BUF_EXT) ? ext_in : d_S;

    ull acc[4][4];
    {
        float4 b4 = __ldg((const float4*)(bias + 4 * tx));
#pragma unroll
        for (int p = 0; p < 4; p++) {
            acc[p][0] = dup2(b4.x); acc[p][1] = dup2(b4.y);
            acc[p][2] = dup2(b4.z); acc[p][3] = dup2(b4.w);
        }
    }
#pragma unroll
    for (int kc = 0; kc < HDIM; kc += KC) {
        __syncthreads();
        load_w_chunk(Ws, W, kc, tid);
        load_a_chunk<HDIM, SCALE_IN>(As, in, m0, kc, tid, nn);
        __syncthreads();
        mma_chunk(acc, As, Ws, tx, ty);
    }

#pragma unroll
    for (int p = 0; p < 4; p++) {
        float4 re, ro;
        unpack2(acc[p][0], re.x, ro.x);
        unpack2(acc[p][1], re.y, ro.y);
        unpack2(acc[p][2], re.z, ro.z);
        unpack2(acc[p][3], re.w, ro.w);
        int ge = m0 + 8 * ty + 2 * p;
        int go = ge + 1;
        if (RELU) {
            re.x = fmaxf(re.x, 0.f); re.y = fmaxf(re.y, 0.f);
            re.z = fmaxf(re.z, 0.f); re.w = fmaxf(re.w, 0.f);
            ro.x = fmaxf(ro.x, 0.f); ro.y = fmaxf(ro.y, 0.f);
            ro.z = fmaxf(ro.z, 0.f); ro.w = fmaxf(ro.w, 0.f);
        }
        if (ge < nn) {
            if (SCALE_OUT) {
                float dv = d_dinv[ge];
                re.x *= dv; re.y *= dv; re.z *= dv; re.w *= dv;
            }
            if (OUT_DST == BUF_S) store_g_half(ge, tx, re);
            else *(float4*)&ext_out[(size_t)ge * HDIM + 4 * tx] = re;
        }
        if (go < nn) {
            if (SCALE_OUT) {
                float dv = d_dinv[go];
                ro.x *= dv; ro.y *= dv; ro.z *= dv; ro.w *= dv;
            }
            if (OUT_DST == BUF_S) store_g_half(go, tx, ro);
            else *(float4*)&ext_out[(size_t)go * HDIM + 4 * tx] = ro;
        }
    }
}

// ------------------------------------------------------------------
// launch: 0 zero  1 fill  2 pad  3 gemmA(profiled)  4 gather1  5 gemmB
//         6 gather2  7 gemmC
// ------------------------------------------------------------------
extern "C" void kernel_launch(void* const* d_in, const int* in_sizes, int n_in,
                              void* d_out, int out_size) {
    const float* x     = (const float*)d_in[0];
    const int*   ei    = (const int*)d_in[1];     // int32 edge indices
    const float* W_in  = (const float*)d_in[2];
    const float* b_in  = (const float*)d_in[3];
    const float* W1    = (const float*)d_in[4];
    const float* b1    = (const float*)d_in[5];
    const float* W2    = (const float*)d_in[6];
    const float* b2    = (const float*)d_in[7];
    const float* W_out = (const float*)d_in[8];
    const float* b_out = (const float*)d_in[9];
    float* out = (float*)d_out;

    int N = in_sizes[0] / 128;   // 100000
    int E = in_sizes[1] / 2;     // 1600000
    const int* e0 = ei;
    const int* e1 = ei + E;

    int tileBlocks = (N + MT - 1) / MT;
    int gatherBlocks = (N + 7) / 8;

    zero_cnt_kernel<<<(N + 255) / 256, 256>>>(N);
    fill_adj_kernel<<<(E + 255) / 256, 256>>>(e0, e1, E);
    pad_adj_kernel<<<(N + 255) / 256, 256>>>(N);

    // fused: h = x@W_in+b_in; g = dinv*relu(h@W1+b1) -> fp16; dinv  (profiled)
    gemm_fused_A<<<tileBlocks, 256>>>(x, W_in, b_in, W1, b1, N);

    // propagate 1
    gather_kernel<<<gatherBlocks, 256>>>(N);

    // g = dinv * relu((dinv*S)@W2 + b2) -> d_gh (fp16)
    gemm_tiled<BUF_S, BUF_S, true, true, true>
        <<<tileBlocks, 256>>>(nullptr, nullptr, W2, b2, N);

    // propagate 2
    gather_kernel<<<gatherBlocks, 256>>>(N);

    // out = (dinv*S) @ W_out + b_out  (fp32)
    gemm_tiled<BUF_S, BUF_EXT, true, false, false>
        <<<tileBlocks, 256>>>(nullptr, out, W_out, b_out, N);
}

// round 13
// speedup vs baseline: 1.1214x; 1.0013x over previous
#include <cuda_runtime.h>
#include <cuda_fp16.h>

#define NMAX 100000
#define HDIM 64
#define SLOTS 128     // max degree safety: Poisson(32) max over 100k nodes ~58

// ---- device scratch (no allocations allowed), 16B-aligned ----
__device__ __align__(16) int     d_cnt [NMAX];
__device__ __align__(16) int     d_adj [(size_t)NMAX * SLOTS];  // padded adjacency
__device__ __align__(16) float   d_dinv[NMAX];
// +1 row: dummy zero node (index NMAX) used for tail padding
__device__ __align__(16) __half2 d_gh[(size_t)(NMAX + 1) * (HDIM / 2)];
__device__ __align__(16) float   d_S [(size_t)NMAX * HDIM];     // propagate result (fp32)

#define BUF_EXT 0
#define BUF_S   1

// ---- packed f32x2 helpers (Blackwell FFMA2 via PTX) ----
typedef unsigned long long ull;
__device__ __forceinline__ ull pack2(float lo, float hi) {
    ull r; asm("mov.b64 %0, {%1, %2};" : "=l"(r) : "f"(lo), "f"(hi)); return r;
}
__device__ __forceinline__ ull dup2(float v) {
    ull r; asm("mov.b64 %0, {%1, %1};" : "=l"(r) : "f"(v)); return r;
}
__device__ __forceinline__ void unpack2(ull v, float& lo, float& hi) {
    asm("mov.b64 {%0, %1}, %2;" : "=f"(lo), "=f"(hi) : "l"(v));
}
__device__ __forceinline__ void fma2(ull& d, ull a, ull b) {
    asm("fma.rn.f32x2 %0, %1, %2, %3;" : "=l"(d) : "l"(a), "l"(b), "l"(d));
}
__device__ __forceinline__ __half2 u2h2(unsigned int u) {
    __half2 h; *(unsigned int*)&h = u; return h;
}

// ------------------------------------------------------------------
// adjacency build (edge_index is int32: JAX x64 disabled)
// ------------------------------------------------------------------
__global__ void zero_cnt_kernel(int n) {
    int i = blockIdx.x * blockDim.x + threadIdx.x;
    if (i < n) d_cnt[i] = 0;
    if (i < 32)   // zero the dummy gather row (row NMAX of d_gh)
        ((unsigned int*)&d_gh[(size_t)NMAX * 32])[i] = 0u;
}

__global__ void fill_adj_kernel(const int* __restrict__ e0,
                                const int* __restrict__ e1, int E) {
    int e = blockIdx.x * blockDim.x + threadIdx.x;
    if (e >= E) return;
    int u = __ldg(&e0[e]);
    int v = __ldg(&e1[e]);
    int pu = atomicAdd(&d_cnt[u], 1);
    if (pu < SLOTS) d_adj[(size_t)u * SLOTS + pu] = v;
    int pv = atomicAdd(&d_cnt[v], 1);
    if (pv < SLOTS) d_adj[(size_t)v * SLOTS + pv] = u;
}

// pad each adjacency list with dummy node NMAX up to a multiple of 8
__global__ void pad_adj_kernel(int nn) {
    int i = blockIdx.x * blockDim.x + threadIdx.x;
    if (i >= nn) return;
    int c = min(d_cnt[i], SLOTS);
    int r = min((c + 7) & ~7, SLOTS);
    for (int t = c; t < r; t++) d_adj[(size_t)i * SLOTS + t] = NMAX;
}

// ------------------------------------------------------------------
// propagate (gather-only): S[i] = sum_{j in adj[i]} g[j]
// warp per node; half-warp w owns a neighbor substream; lane covers 4 cols
// (LDG.64); fp16 group accumulation (8 nbrs) + fp32 flush. No tail.
// ------------------------------------------------------------------
__global__ __launch_bounds__(256)
void gather_kernel(int nn) {
    int node = blockIdx.x * 8 + (threadIdx.x >> 5);
    int lane = threadIdx.x & 31;
    if (node >= nn) return;
    int w = lane >> 4;         // half-warp id (neighbor substream)
    int c = lane & 15;         // column quad: cols 4c..4c+3
    int cnt = min(d_cnt[node], SLOTS);
    int cntp = min((cnt + 7) & ~7, SLOTS);   // padded length (multiple of 8)
    const int* adj = &d_adj[(size_t)node * SLOTS];
    const uint2* gh2 = (const uint2*)d_gh;   // 4 halves per uint2; node row = 16 uint2

    float4 facc = make_float4(0.f, 0.f, 0.f, 0.f);

    int4 nb = make_int4(NMAX, NMAX, NMAX, NMAX);
    if (cntp > 0) nb = __ldg((const int4*)&adj[4 * w]);
    for (int j = 0; j < cntp; j += 8) {
        int4 cur = nb;
        if (j + 8 < cntp)                                // prefetch next group
            nb = __ldg((const int4*)&adj[j + 8 + 4 * w]);
        uint2 v0 = __ldg(&gh2[(size_t)cur.x * 16 + c]);
        uint2 v1 = __ldg(&gh2[(size_t)cur.y * 16 + c]);
        uint2 v2 = __ldg(&gh2[(size_t)cur.z * 16 + c]);
        uint2 v3 = __ldg(&gh2[(size_t)cur.w * 16 + c]);
        __half2 h0 = __hadd2(__hadd2(u2h2(v0.x), u2h2(v1.x)),
                             __hadd2(u2h2(v2.x), u2h2(v3.x)));
        __half2 h1 = __hadd2(__hadd2(u2h2(v0.y), u2h2(v1.y)),
                             __hadd2(u2h2(v2.y), u2h2(v3.y)));
        float2 f0 = __half22float2(h0);
        float2 f1 = __half22float2(h1);
        facc.x += f0.x; facc.y += f0.y; facc.z += f1.x; facc.w += f1.y;
    }
    // combine the two half-warp substreams (lanes c and c+16 hold same cols)
    facc.x += __shfl_xor_sync(0xffffffffu, facc.x, 16);
    facc.y += __shfl_xor_sync(0xffffffffu, facc.y, 16);
    facc.z += __shfl_xor_sync(0xffffffffu, facc.z, 16);
    facc.w += __shfl_xor_sync(0xffffffffu, facc.w, 16);
    if (w == 0)
        ((float4*)d_S)[(size_t)node * 16 + c] = facc;   // overwrite, no zeroing
}

// ==================================================================
// Tiled GEMM machinery: 128-node x 64-col tile, 256 threads,
// thread = 8 nodes (4 node-pairs) x 4 cols, FFMA2 inner product.
// ==================================================================
#define MT 128
#define KC 32
#define AS_PITCH 132
#define HS_PITCH 68

__device__ __forceinline__ void load_w_chunk(float* sWs, const float* W, int kc, int tid) {
#pragma unroll
    for (int l = 0; l < (KC * HDIM / 4) / 256; l++) {
        int idx = tid + l * 256;
        int k = idx >> 4, c4 = idx & 15;
        *(float4*)&sWs[k * HDIM + 4 * c4] =
            __ldg((const float4*)(W + (size_t)(kc + k) * HDIM + 4 * c4));
    }
}

template<int KP, bool SCALE_IN>
__device__ __forceinline__ void load_a_chunk(float* sAs, const float* in,
                                             int m0, int kc, int tid, int nn) {
#pragma unroll
    for (int l = 0; l < (MT * (KC / 4)) / 256; l++) {
        int idx = tid + l * 256;
        int node = idx >> 3, kq = idx & 7;
        int gm = m0 + node;
        float4 av = make_float4(0.f, 0.f, 0.f, 0.f);
        if (gm < nn) {
            av = __ldg((const float4*)(in + (size_t)gm * KP + kc + 4 * kq));
            if (SCALE_IN) {
                float dv = d_dinv[gm];
                av.x *= dv; av.y *= dv; av.z *= dv; av.w *= dv;
            }
        }
        sAs[(4 * kq + 0) * AS_PITCH + node] = av.x;
        sAs[(4 * kq + 1) * AS_PITCH + node] = av.y;
        sAs[(4 * kq + 2) * AS_PITCH + node] = av.z;
        sAs[(4 * kq + 3) * AS_PITCH + node] = av.w;
    }
}

__device__ __forceinline__ void mma_chunk(ull acc[4][4], const float* sAs,
                                          const float* sWs, int tx, int ty) {
#pragma unroll
    for (int k = 0; k < KC; k++) {
        ulonglong2 a01 = *(const ulonglong2*)&sAs[k * AS_PITCH + 8 * ty];
        ulonglong2 a23 = *(const ulonglong2*)&sAs[k * AS_PITCH + 8 * ty + 4];
        float4 wv = *(const float4*)&sWs[k * HDIM + 4 * tx];
        ull w0 = dup2(wv.x), w1 = dup2(wv.y), w2 = dup2(wv.z), w3 = dup2(wv.w);
        fma2(acc[0][0], a01.x, w0); fma2(acc[0][1], a01.x, w1);
        fma2(acc[0][2], a01.x, w2); fma2(acc[0][3], a01.x, w3);
        fma2(acc[1][0], a01.y, w0); fma2(acc[1][1], a01.y, w1);
        fma2(acc[1][2], a01.y, w2); fma2(acc[1][3], a01.y, w3);
        fma2(acc[2][0], a23.x, w0); fma2(acc[2][1], a23.x, w1);
        fma2(acc[2][2], a23.x, w2); fma2(acc[2][3], a23.x, w3);
        fma2(acc[3][0], a23.y, w0); fma2(acc[3][1], a23.y, w1);
        fma2(acc[3][2], a23.y, w2); fma2(acc[3][3], a23.y, w3);
    }
}

// store a relu+scale'd float4 (4 cols at 4*tx) into d_gh as 2 half2 (one STG.64)
__device__ __forceinline__ void store_g_half(int gm, int tx, float4 r) {
    __half2 h0 = __floats2half2_rn(r.x, r.y);
    __half2 h1 = __floats2half2_rn(r.z, r.w);
    uint2 pk;
    pk.x = *(unsigned int*)&h0;
    pk.y = *(unsigned int*)&h1;
    *(uint2*)&d_gh[(size_t)gm * 32 + 2 * tx] = pk;
}

// ------------------------------------------------------------------
// gemmA (fused): h = x@W_in+b_in (SMEM); g = dinv*relu(h@W1+b1) -> d_gh (fp16)
// phase 2 loads h as float4 over k (LDS.128) + hoisted W row-pairs.
// ------------------------------------------------------------------
__global__ __launch_bounds__(256, 3)
void gemm_fused_A(const float* __restrict__ x,
                  const float* __restrict__ W_in, const float* __restrict__ b_in,
                  const float* __restrict__ W1,   const float* __restrict__ b1,
                  int nn) {
    __shared__ __align__(16) float sU[MT * HS_PITCH];
    __shared__ __align__(16) float sW2[KC * HDIM];
    float* As = sU;
    float* Ws = sU + KC * AS_PITCH;
    float* Hs = sU;

    int tid = threadIdx.x;
    int tx = tid & 15, ty = tid >> 4;
    int m0 = blockIdx.x * MT;

    // phase 1: h = x @ W_in + b_in
    ull acc[4][4];
    {
        float4 b4 = __ldg((const float4*)(b_in + 4 * tx));
#pragma unroll
        for (int p = 0; p < 4; p++) {
            acc[p][0] = dup2(b4.x); acc[p][1] = dup2(b4.y);
            acc[p][2] = dup2(b4.z); acc[p][3] = dup2(b4.w);
        }
    }
#pragma unroll
    for (int kc = 0; kc < 128; kc += KC) {
        __syncthreads();
        load_w_chunk(Ws, W_in, kc, tid);
        load_a_chunk<128, false>(As, x, m0, kc, tid, nn);
        __syncthreads();
        mma_chunk(acc, As, Ws, tx, ty);
    }
    __syncthreads();
#pragma unroll
    for (int p = 0; p < 4; p++) {
        float4 re, ro;
        unpack2(acc[p][0], re.x, ro.x);
        unpack2(acc[p][1], re.y, ro.y);
        unpack2(acc[p][2], re.z, ro.z);
        unpack2(acc[p][3], re.w, ro.w);
        *(float4*)&Hs[(8 * ty + 2 * p)     * HS_PITCH + 4 * tx] = re;
        *(float4*)&Hs[(8 * ty + 2 * p + 1) * HS_PITCH + 4 * tx] = ro;
    }
    __syncthreads();

    // phase 2: g = dinv * relu(h @ W1 + b1)
    // per k-quad: 4 hoisted W row-pairs + per node one LDS.128 of h[k..k+3]
    ull acc2[8][2];
    {
        float4 b4 = __ldg((const float4*)(b1 + 4 * tx));
#pragma unroll
        for (int n = 0; n < 8; n++) {
            acc2[n][0] = pack2(b4.x, b4.y);
            acc2[n][1] = pack2(b4.z, b4.w);
        }
    }
#pragma unroll
    for (int kc = 0; kc < HDIM; kc += KC) {
        __syncthreads();
        load_w_chunk(sW2, W1, kc, tid);
        __syncthreads();
#pragma unroll
        for (int k4 = 0; k4 < KC / 4; k4++) {
            ulonglong2 wr0 = *(const ulonglong2*)&sW2[(4 * k4 + 0) * HDIM + 4 * tx];
            ulonglong2 wr1 = *(const ulonglong2*)&sW2[(4 * k4 + 1) * HDIM + 4 * tx];
            ulonglong2 wr2 = *(const ulonglong2*)&sW2[(4 * k4 + 2) * HDIM + 4 * tx];
            ulonglong2 wr3 = *(const ulonglong2*)&sW2[(4 * k4 + 3) * HDIM + 4 * tx];
#pragma unroll
            for (int n = 0; n < 8; n++) {
                float4 h4 = *(const float4*)&Hs[(8 * ty + n) * HS_PITCH + kc + 4 * k4];
                ull a0 = dup2(h4.x), a1 = dup2(h4.y), a2 = dup2(h4.z), a3 = dup2(h4.w);
                fma2(acc2[n][0], a0, wr0.x); fma2(acc2[n][1], a0, wr0.y);
                fma2(acc2[n][0], a1, wr1.x); fma2(acc2[n][1], a1, wr1.y);
                fma2(acc2[n][0], a2, wr2.x); fma2(acc2[n][1], a2, wr2.y);
                fma2(acc2[n][0], a3, wr3.x); fma2(acc2[n][1], a3, wr3.y);
            }
        }
    }

    // epilogue: dinv from counts, relu, scale, store g (fp16)
#pragma unroll
    for (int n = 0; n < 8; n++) {
        int gm = m0 + 8 * ty + n;
        if (gm < nn) {
            int c = d_cnt[gm];
            float dv = c > 0 ? rsqrtf((float)c) : 0.0f;
            if (tx == 0) d_dinv[gm] = dv;
            float4 r;
            unpack2(acc2[n][0], r.x, r.y);
            unpack2(acc2[n][1], r.z, r.w);
            r.x = fmaxf(r.x, 0.f) * dv; r.y = fmaxf(r.y, 0.f) * dv;
            r.z = fmaxf(r.z, 0.f) * dv; r.w = fmaxf(r.w, 0.f) * dv;
            store_g_half(gm, tx, r);
        }
    }
}

// ------------------------------------------------------------------
// single tiled GEMM (K=64): out = f((maybe dinv*in) @ W + b)
// OUT_DST==BUF_S -> writes d_gh (fp16); BUF_EXT -> fp32 external out
// ------------------------------------------------------------------
template<int IN_SRC, int OUT_DST, bool SCALE_IN, bool RELU, bool SCALE_OUT>
__global__ __launch_bounds__(256, 3)
void gemm_tiled(const float* __restrict__ ext_in, float* __restrict__ ext_out,
                const float* __restrict__ W, const float* __restrict__ bias, int nn) {
    __shared__ __align__(16) float As[KC * AS_PITCH];
    __shared__ __align__(16) float Ws[KC * HDIM];

    int tid = threadIdx.x;
    int tx = tid & 15, ty = tid >> 4;
    int m0 = blockIdx.x * MT;

    const float* in = (IN_SRC == BUF_EXT) ? ext_in : d_S;

    ull acc[4][4];
    {
        float4 b4 = __ldg((const float4*)(bias + 4 * tx));
#pragma unroll
        for (int p = 0; p < 4; p++) {
            acc[p][0] = dup2(b4.x); acc[p][1] = dup2(b4.y);
            acc[p][2] = dup2(b4.z); acc[p][3] = dup2(b4.w);
        }
    }
#pragma unroll
    for (int kc = 0; kc < HDIM; kc += KC) {
        __syncthreads();
        load_w_chunk(Ws, W, kc, tid);
        load_a_chunk<HDIM, SCALE_IN>(As, in, m0, kc, tid, nn);
        __syncthreads();
        mma_chunk(acc, As, Ws, tx, ty);
    }

#pragma unroll
    for (int p = 0; p < 4; p++) {
        float4 re, ro;
        unpack2(acc[p][0], re.x, ro.x);
        unpack2(acc[p][1], re.y, ro.y);
        unpack2(acc[p][2], re.z, ro.z);
        unpack2(acc[p][3], re.w, ro.w);
        int ge = m0 + 8 * ty + 2 * p;
        int go = ge + 1;
        if (RELU) {
            re.x = fmaxf(re.x, 0.f); re.y = fmaxf(re.y, 0.f);
            re.z = fmaxf(re.z, 0.f); re.w = fmaxf(re.w, 0.f);
            ro.x = fmaxf(ro.x, 0.f); ro.y = fmaxf(ro.y, 0.f);
            ro.z = fmaxf(ro.z, 0.f); ro.w = fmaxf(ro.w, 0.f);
        }
        if (ge < nn) {
            if (SCALE_OUT) {
                float dv = d_dinv[ge];
                re.x *= dv; re.y *= dv; re.z *= dv; re.w *= dv;
            }
            if (OUT_DST == BUF_S) store_g_half(ge, tx, re);
            else *(float4*)&ext_out[(size_t)ge * HDIM + 4 * tx] = re;
        }
        if (go < nn) {
            if (SCALE_OUT) {
                float dv = d_dinv[go];
                ro.x *= dv; ro.y *= dv; ro.z *= dv; ro.w *= dv;
            }
            if (OUT_DST == BUF_S) store_g_half(go, tx, ro);
            else *(float4*)&ext_out[(size_t)go * HDIM + 4 * tx] = ro;
        }
    }
}

// ------------------------------------------------------------------
// launch: 0 zero  1 fill  2 pad  3 gemmA(profiled)  4 gather1  5 gemmB
//         6 gather2  7 gemmC
// ------------------------------------------------------------------
extern "C" void kernel_launch(void* const* d_in, const int* in_sizes, int n_in,
                              void* d_out, int out_size) {
    const float* x     = (const float*)d_in[0];
    const int*   ei    = (const int*)d_in[1];     // int32 edge indices
    const float* W_in  = (const float*)d_in[2];
    const float* b_in  = (const float*)d_in[3];
    const float* W1    = (const float*)d_in[4];
    const float* b1    = (const float*)d_in[5];
    const float* W2    = (const float*)d_in[6];
    const float* b2    = (const float*)d_in[7];
    const float* W_out = (const float*)d_in[8];
    const float* b_out = (const float*)d_in[9];
    float* out = (float*)d_out;

    int N = in_sizes[0] / 128;   // 100000
    int E = in_sizes[1] / 2;     // 1600000
    const int* e0 = ei;
    const int* e1 = ei + E;

    int tileBlocks = (N + MT - 1) / MT;
    int gatherBlocks = (N + 7) / 8;

    zero_cnt_kernel<<<(N + 255) / 256, 256>>>(N);
    fill_adj_kernel<<<(E + 255) / 256, 256>>>(e0, e1, E);
    pad_adj_kernel<<<(N + 255) / 256, 256>>>(N);

    // fused: h = x@W_in+b_in; g = dinv*relu(h@W1+b1) -> fp16; dinv  (profiled)
    gemm_fused_A<<<tileBlocks, 256>>>(x, W_in, b_in, W1, b1, N);

    // propagate 1
    gather_kernel<<<gatherBlocks, 256>>>(N);

    // g = dinv * relu((dinv*S)@W2 + b2) -> d_gh (fp16)
    gemm_tiled<BUF_S, BUF_S, true, true, true>
        <<<tileBlocks, 256>>>(nullptr, nullptr, W2, b2, N);

    // propagate 2
    gather_kernel<<<gatherBlocks, 256>>>(N);

    // out = (dinv*S) @ W_out + b_out  (fp32)
    gemm_tiled<BUF_S, BUF_EXT, true, false, false>
        <<<tileBlocks, 256>>>(nullptr, out, W_out, b_out, N);
}

// round 14
// speedup vs baseline: 1.1339x; 1.0111x over previous
#include <cuda_runtime.h>
#include <cuda_fp16.h>

#define NMAX 100000
#define HDIM 64
#define SLOTS 128     // max degree safety: Poisson(32) max over 100k nodes ~58

// ---- device scratch (no allocations allowed), 16B-aligned ----
__device__ __align__(16) int     d_cnt [NMAX];
__device__ __align__(16) int     d_adj [(size_t)NMAX * SLOTS];  // padded adjacency
__device__ __align__(16) float   d_dinv[NMAX];
// +1 row: dummy zero node (index NMAX) used for tail padding
__device__ __align__(16) __half2 d_gh[(size_t)(NMAX + 1) * (HDIM / 2)];
__device__ __align__(16) float   d_S [(size_t)NMAX * HDIM];     // propagate result (fp32)

#define BUF_EXT 0
#define BUF_S   1

// ---- packed f32x2 helpers (Blackwell FFMA2 via PTX) ----
typedef unsigned long long ull;
__device__ __forceinline__ ull pack2(float lo, float hi) {
    ull r; asm("mov.b64 %0, {%1, %2};" : "=l"(r) : "f"(lo), "f"(hi)); return r;
}
__device__ __forceinline__ ull dup2(float v) {
    ull r; asm("mov.b64 %0, {%1, %1};" : "=l"(r) : "f"(v)); return r;
}
__device__ __forceinline__ void unpack2(ull v, float& lo, float& hi) {
    asm("mov.b64 {%0, %1}, %2;" : "=f"(lo), "=f"(hi) : "l"(v));
}
__device__ __forceinline__ void fma2(ull& d, ull a, ull b) {
    asm("fma.rn.f32x2 %0, %1, %2, %3;" : "=l"(d) : "l"(a), "l"(b), "l"(d));
}
__device__ __forceinline__ __half2 u2h2(unsigned int u) {
    __half2 h; *(unsigned int*)&h = u; return h;
}

// ------------------------------------------------------------------
// adjacency build (edge_index is int32: JAX x64 disabled)
// ------------------------------------------------------------------
__global__ void zero_cnt_kernel(int n) {
    int i = blockIdx.x * blockDim.x + threadIdx.x;
    if (i < n) d_cnt[i] = 0;
    if (i < 32)   // zero the dummy gather row (row NMAX of d_gh)
        ((unsigned int*)&d_gh[(size_t)NMAX * 32])[i] = 0u;
}

__global__ void fill_adj_kernel(const int* __restrict__ e0,
                                const int* __restrict__ e1, int E) {
    int e = blockIdx.x * blockDim.x + threadIdx.x;
    if (e >= E) return;
    int u = __ldg(&e0[e]);
    int v = __ldg(&e1[e]);
    int pu = atomicAdd(&d_cnt[u], 1);
    if (pu < SLOTS) d_adj[(size_t)u * SLOTS + pu] = v;
    int pv = atomicAdd(&d_cnt[v], 1);
    if (pv < SLOTS) d_adj[(size_t)v * SLOTS + pv] = u;
}

// pad each adjacency list with dummy node NMAX up to a multiple of 8
__global__ void pad_adj_kernel(int nn) {
    int i = blockIdx.x * blockDim.x + threadIdx.x;
    if (i >= nn) return;
    int c = min(d_cnt[i], SLOTS);
    int r = min((c + 7) & ~7, SLOTS);
    for (int t = c; t < r; t++) d_adj[(size_t)i * SLOTS + t] = NMAX;
}

// ------------------------------------------------------------------
// propagate (gather-only): S[i] = sum_{j in adj[i]} g[j]
// ------------------------------------------------------------------
__global__ __launch_bounds__(256)
void gather_kernel(int nn) {
    int node = blockIdx.x * 8 + (threadIdx.x >> 5);
    int lane = threadIdx.x & 31;
    if (node >= nn) return;
    int w = lane >> 4;         // half-warp id (neighbor substream)
    int c = lane & 15;         // column quad: cols 4c..4c+3
    int cnt = min(d_cnt[node], SLOTS);
    int cntp = min((cnt + 7) & ~7, SLOTS);   // padded length (multiple of 8)
    const int* adj = &d_adj[(size_t)node * SLOTS];
    const uint2* gh2 = (const uint2*)d_gh;

    float4 facc = make_float4(0.f, 0.f, 0.f, 0.f);

    int4 nb = make_int4(NMAX, NMAX, NMAX, NMAX);
    if (cntp > 0) nb = __ldg((const int4*)&adj[4 * w]);
    for (int j = 0; j < cntp; j += 8) {
        int4 cur = nb;
        if (j + 8 < cntp)
            nb = __ldg((const int4*)&adj[j + 8 + 4 * w]);
        uint2 v0 = __ldg(&gh2[(size_t)cur.x * 16 + c]);
        uint2 v1 = __ldg(&gh2[(size_t)cur.y * 16 + c]);
        uint2 v2 = __ldg(&gh2[(size_t)cur.z * 16 + c]);
        uint2 v3 = __ldg(&gh2[(size_t)cur.w * 16 + c]);
        __half2 h0 = __hadd2(__hadd2(u2h2(v0.x), u2h2(v1.x)),
                             __hadd2(u2h2(v2.x), u2h2(v3.x)));
        __half2 h1 = __hadd2(__hadd2(u2h2(v0.y), u2h2(v1.y)),
                             __hadd2(u2h2(v2.y), u2h2(v3.y)));
        float2 f0 = __half22float2(h0);
        float2 f1 = __half22float2(h1);
        facc.x += f0.x; facc.y += f0.y; facc.z += f1.x; facc.w += f1.y;
    }
    facc.x += __shfl_xor_sync(0xffffffffu, facc.x, 16);
    facc.y += __shfl_xor_sync(0xffffffffu, facc.y, 16);
    facc.z += __shfl_xor_sync(0xffffffffu, facc.z, 16);
    facc.w += __shfl_xor_sync(0xffffffffu, facc.w, 16);
    if (w == 0)
        ((float4*)d_S)[(size_t)node * 16 + c] = facc;
}

// ==================================================================
// Tiled GEMM machinery (software-pipelined): 128-node x 64-col tile,
// 256 threads, thread = 8 nodes x 4 cols, FFMA2 inner product.
// LDG of chunk i+1 issued BEFORE mma of chunk i (register staging).
// ==================================================================
#define MT 128
#define KC 32
#define AS_PITCH 132
#define HS_PITCH 68

// --- split load: ldg to regs / sts to smem ---
__device__ __forceinline__ void ldg_w(float4 wr[2], const float* W, int kc, int tid) {
#pragma unroll
    for (int l = 0; l < 2; l++) {
        int idx = tid + l * 256;
        int k = idx >> 4, c4 = idx & 15;
        wr[l] = __ldg((const float4*)(W + (size_t)(kc + k) * HDIM + 4 * c4));
    }
}
__device__ __forceinline__ void sts_w(const float4 wr[2], float* sWs, int tid) {
#pragma unroll
    for (int l = 0; l < 2; l++) {
        int idx = tid + l * 256;
        int k = idx >> 4, c4 = idx & 15;
        *(float4*)&sWs[k * HDIM + 4 * c4] = wr[l];
    }
}

template<int KP, bool SCALE_IN>
__device__ __forceinline__ void ldg_a(float4 ar[4], const float* in,
                                      int m0, int kc, int tid, int nn) {
#pragma unroll
    for (int l = 0; l < 4; l++) {
        int idx = tid + l * 256;
        int node = idx >> 3, kq = idx & 7;
        int gm = m0 + node;
        float4 av = make_float4(0.f, 0.f, 0.f, 0.f);
        if (gm < nn) {
            av = __ldg((const float4*)(in + (size_t)gm * KP + kc + 4 * kq));
            if (SCALE_IN) {
                float dv = d_dinv[gm];
                av.x *= dv; av.y *= dv; av.z *= dv; av.w *= dv;
            }
        }
        ar[l] = av;
    }
}
__device__ __forceinline__ void sts_a(const float4 ar[4], float* sAs, int tid) {
#pragma unroll
    for (int l = 0; l < 4; l++) {
        int idx = tid + l * 256;
        int node = idx >> 3, kq = idx & 7;
        sAs[(4 * kq + 0) * AS_PITCH + node] = ar[l].x;
        sAs[(4 * kq + 1) * AS_PITCH + node] = ar[l].y;
        sAs[(4 * kq + 2) * AS_PITCH + node] = ar[l].z;
        sAs[(4 * kq + 3) * AS_PITCH + node] = ar[l].w;
    }
}

__device__ __forceinline__ void mma_chunk(ull acc[4][4], const float* sAs,
                                          const float* sWs, int tx, int ty) {
#pragma unroll
    for (int k = 0; k < KC; k++) {
        ulonglong2 a01 = *(const ulonglong2*)&sAs[k * AS_PITCH + 8 * ty];
        ulonglong2 a23 = *(const ulonglong2*)&sAs[k * AS_PITCH + 8 * ty + 4];
        float4 wv = *(const float4*)&sWs[k * HDIM + 4 * tx];
        ull w0 = dup2(wv.x), w1 = dup2(wv.y), w2 = dup2(wv.z), w3 = dup2(wv.w);
        fma2(acc[0][0], a01.x, w0); fma2(acc[0][1], a01.x, w1);
        fma2(acc[0][2], a01.x, w2); fma2(acc[0][3], a01.x, w3);
        fma2(acc[1][0], a01.y, w0); fma2(acc[1][1], a01.y, w1);
        fma2(acc[1][2], a01.y, w2); fma2(acc[1][3], a01.y, w3);
        fma2(acc[2][0], a23.x, w0); fma2(acc[2][1], a23.x, w1);
        fma2(acc[2][2], a23.x, w2); fma2(acc[2][3], a23.x, w3);
        fma2(acc[3][0], a23.y, w0); fma2(acc[3][1], a23.y, w1);
        fma2(acc[3][2], a23.y, w2); fma2(acc[3][3], a23.y, w3);
    }
}

// store a relu+scale'd float4 (4 cols at 4*tx) into d_gh as 2 half2 (one STG.64)
__device__ __forceinline__ void store_g_half(int gm, int tx, float4 r) {
    __half2 h0 = __floats2half2_rn(r.x, r.y);
    __half2 h1 = __floats2half2_rn(r.z, r.w);
    uint2 pk;
    pk.x = *(unsigned int*)&h0;
    pk.y = *(unsigned int*)&h1;
    *(uint2*)&d_gh[(size_t)gm * 32 + 2 * tx] = pk;
}

// ------------------------------------------------------------------
// gemmA (fused, pipelined): h = x@W_in+b_in (SMEM);
// g = dinv*relu(h@W1+b1) -> d_gh (fp16); dinv from d_cnt.
// ------------------------------------------------------------------
__global__ __launch_bounds__(256, 2)
void gemm_fused_A(const float* __restrict__ x,
                  const float* __restrict__ W_in, const float* __restrict__ b_in,
                  const float* __restrict__ W1,   const float* __restrict__ b1,
                  int nn) {
    __shared__ __align__(16) float sU[MT * HS_PITCH];
    __shared__ __align__(16) float sW2[KC * HDIM];
    float* As = sU;
    float* Ws = sU + KC * AS_PITCH;
    float* Hs = sU;

    int tid = threadIdx.x;
    int tx = tid & 15, ty = tid >> 4;
    int m0 = blockIdx.x * MT;

    // phase 1: h = x @ W_in + b_in  (pipelined over 4 chunks)
    ull acc[4][4];
    {
        float4 b4 = __ldg((const float4*)(b_in + 4 * tx));
#pragma unroll
        for (int p = 0; p < 4; p++) {
            acc[p][0] = dup2(b4.x); acc[p][1] = dup2(b4.y);
            acc[p][2] = dup2(b4.z); acc[p][3] = dup2(b4.w);
        }
    }
    float4 ar[4], wr[2];
    ldg_a<128, false>(ar, x, m0, 0, tid, nn);
    ldg_w(wr, W_in, 0, tid);
#pragma unroll
    for (int kc = 0; kc < 128; kc += KC) {
        __syncthreads();                       // prior mma done reading smem
        sts_a(ar, As, tid);
        sts_w(wr, Ws, tid);
        __syncthreads();
        if (kc + KC < 128) {                   // prefetch next chunk
            ldg_a<128, false>(ar, x, m0, kc + KC, tid, nn);
            ldg_w(wr, W_in, kc + KC, tid);
        }
        mma_chunk(acc, As, Ws, tx, ty);        // overlaps with LDGs in flight
    }
    ldg_w(wr, W1, 0, tid);                     // prefetch phase-2 W chunk 0
    __syncthreads();
#pragma unroll
    for (int p = 0; p < 4; p++) {
        float4 re, ro;
        unpack2(acc[p][0], re.x, ro.x);
        unpack2(acc[p][1], re.y, ro.y);
        unpack2(acc[p][2], re.z, ro.z);
        unpack2(acc[p][3], re.w, ro.w);
        *(float4*)&Hs[(8 * ty + 2 * p)     * HS_PITCH + 4 * tx] = re;
        *(float4*)&Hs[(8 * ty + 2 * p + 1) * HS_PITCH + 4 * tx] = ro;
    }
    __syncthreads();

    // phase 2: g = dinv * relu(h @ W1 + b1)  (W chunks pipelined)
    ull acc2[8][2];
    {
        float4 b4 = __ldg((const float4*)(b1 + 4 * tx));
#pragma unroll
        for (int n = 0; n < 8; n++) {
            acc2[n][0] = pack2(b4.x, b4.y);
            acc2[n][1] = pack2(b4.z, b4.w);
        }
    }
#pragma unroll
    for (int kc = 0; kc < HDIM; kc += KC) {
        if (kc) __syncthreads();
        sts_w(wr, sW2, tid);
        __syncthreads();
        if (kc + KC < HDIM) ldg_w(wr, W1, kc + KC, tid);
#pragma unroll
        for (int k4 = 0; k4 < KC / 4; k4++) {
            ulonglong2 wr0 = *(const ulonglong2*)&sW2[(4 * k4 + 0) * HDIM + 4 * tx];
            ulonglong2 wr1 = *(const ulonglong2*)&sW2[(4 * k4 + 1) * HDIM + 4 * tx];
            ulonglong2 wr2 = *(const ulonglong2*)&sW2[(4 * k4 + 2) * HDIM + 4 * tx];
            ulonglong2 wr3 = *(const ulonglong2*)&sW2[(4 * k4 + 3) * HDIM + 4 * tx];
#pragma unroll
            for (int n = 0; n < 8; n++) {
                float4 h4 = *(const float4*)&Hs[(8 * ty + n) * HS_PITCH + kc + 4 * k4];
                ull a0 = dup2(h4.x), a1 = dup2(h4.y), a2 = dup2(h4.z), a3 = dup2(h4.w);
                fma2(acc2[n][0], a0, wr0.x); fma2(acc2[n][1], a0, wr0.y);
                fma2(acc2[n][0], a1, wr1.x); fma2(acc2[n][1], a1, wr1.y);
                fma2(acc2[n][0], a2, wr2.x); fma2(acc2[n][1], a2, wr2.y);
                fma2(acc2[n][0], a3, wr3.x); fma2(acc2[n][1], a3, wr3.y);
            }
        }
    }

    // epilogue: dinv from counts, relu, scale, store g (fp16)
#pragma unroll
    for (int n = 0; n < 8; n++) {
        int gm = m0 + 8 * ty + n;
        if (gm < nn) {
            int c = d_cnt[gm];
            float dv = c > 0 ? rsqrtf((float)c) : 0.0f;
            if (tx == 0) d_dinv[gm] = dv;
            float4 r;
            unpack2(acc2[n][0], r.x, r.y);
            unpack2(acc2[n][1], r.z, r.w);
            r.x = fmaxf(r.x, 0.f) * dv; r.y = fmaxf(r.y, 0.f) * dv;
            r.z = fmaxf(r.z, 0.f) * dv; r.w = fmaxf(r.w, 0.f) * dv;
            store_g_half(gm, tx, r);
        }
    }
}

// ------------------------------------------------------------------
// single tiled GEMM (K=64, pipelined): out = f((maybe dinv*in) @ W + b)
// OUT_DST==BUF_S -> writes d_gh (fp16); BUF_EXT -> fp32 external out
// ------------------------------------------------------------------
template<int IN_SRC, int OUT_DST, bool SCALE_IN, bool RELU, bool SCALE_OUT>
__global__ __launch_bounds__(256, 2)
void gemm_tiled(const float* __restrict__ ext_in, float* __restrict__ ext_out,
                const float* __restrict__ W, const float* __restrict__ bias, int nn) {
    __shared__ __align__(16) float As[KC * AS_PITCH];
    __shared__ __align__(16) float Ws[KC * HDIM];

    int tid = threadIdx.x;
    int tx = tid & 15, ty = tid >> 4;
    int m0 = blockIdx.x * MT;

    const float* in = (IN_SRC == BUF_EXT) ? ext_in : d_S;

    ull acc[4][4];
    {
        float4 b4 = __ldg((const float4*)(bias + 4 * tx));
#pragma unroll
        for (int p = 0; p < 4; p++) {
            acc[p][0] = dup2(b4.x); acc[p][1] = dup2(b4.y);
            acc[p][2] = dup2(b4.z); acc[p][3] = dup2(b4.w);
        }
    }
    float4 ar[4], wr[2];
    ldg_a<HDIM, SCALE_IN>(ar, in, m0, 0, tid, nn);
    ldg_w(wr, W, 0, tid);
#pragma unroll
    for (int kc = 0; kc < HDIM; kc += KC) {
        __syncthreads();
        sts_a(ar, As, tid);
        sts_w(wr, Ws, tid);
        __syncthreads();
        if (kc + KC < HDIM) {
            ldg_a<HDIM, SCALE_IN>(ar, in, m0, kc + KC, tid, nn);
            ldg_w(wr, W, kc + KC, tid);
        }
        mma_chunk(acc, As, Ws, tx, ty);
    }

#pragma unroll
    for (int p = 0; p < 4; p++) {
        float4 re, ro;
        unpack2(acc[p][0], re.x, ro.x);
        unpack2(acc[p][1], re.y, ro.y);
        unpack2(acc[p][2], re.z, ro.z);
        unpack2(acc[p][3], re.w, ro.w);
        int ge = m0 + 8 * ty + 2 * p;
        int go = ge + 1;
        if (RELU) {
            re.x = fmaxf(re.x, 0.f); re.y = fmaxf(re.y, 0.f);
            re.z = fmaxf(re.z, 0.f); re.w = fmaxf(re.w, 0.f);
            ro.x = fmaxf(ro.x, 0.f); ro.y = fmaxf(ro.y, 0.f);
            ro.z = fmaxf(ro.z, 0.f); ro.w = fmaxf(ro.w, 0.f);
        }
        if (ge < nn) {
            if (SCALE_OUT) {
                float dv = d_dinv[ge];
                re.x *= dv; re.y *= dv; re.z *= dv; re.w *= dv;
            }
            if (OUT_DST == BUF_S) store_g_half(ge, tx, re);
            else *(float4*)&ext_out[(size_t)ge * HDIM + 4 * tx] = re;
        }
        if (go < nn) {
            if (SCALE_OUT) {
                float dv = d_dinv[go];
                ro.x *= dv; ro.y *= dv; ro.z *= dv; ro.w *= dv;
            }
            if (OUT_DST == BUF_S) store_g_half(go, tx, ro);
            else *(float4*)&ext_out[(size_t)go * HDIM + 4 * tx] = ro;
        }
    }
}

// ------------------------------------------------------------------
// launch: 0 zero  1 fill  2 pad  3 gemmA(profiled)  4 gather1  5 gemmB
//         6 gather2  7 gemmC
// ------------------------------------------------------------------
extern "C" void kernel_launch(void* const* d_in, const int* in_sizes, int n_in,
                              void* d_out, int out_size) {
    const float* x     = (const float*)d_in[0];
    const int*   ei    = (const int*)d_in[1];     // int32 edge indices
    const float* W_in  = (const float*)d_in[2];
    const float* b_in  = (const float*)d_in[3];
    const float* W1    = (const float*)d_in[4];
    const float* b1    = (const float*)d_in[5];
    const float* W2    = (const float*)d_in[6];
    const float* b2    = (const float*)d_in[7];
    const float* W_out = (const float*)d_in[8];
    const float* b_out = (const float*)d_in[9];
    float* out = (float*)d_out;

    int N = in_sizes[0] / 128;   // 100000
    int E = in_sizes[1] / 2;     // 1600000
    const int* e0 = ei;
    const int* e1 = ei + E;

    int tileBlocks = (N + MT - 1) / MT;
    int gatherBlocks = (N + 7) / 8;

    zero_cnt_kernel<<<(N + 255) / 256, 256>>>(N);
    fill_adj_kernel<<<(E + 255) / 256, 256>>>(e0, e1, E);
    pad_adj_kernel<<<(N + 255) / 256, 256>>>(N);

    // fused: h = x@W_in+b_in; g = dinv*relu(h@W1+b1) -> fp16; dinv  (profiled)
    gemm_fused_A<<<tileBlocks, 256>>>(x, W_in, b_in, W1, b1, N);

    // propagate 1
    gather_kernel<<<gatherBlocks, 256>>>(N);

    // g = dinv * relu((dinv*S)@W2 + b2) -> d_gh (fp16)
    gemm_tiled<BUF_S, BUF_S, true, true, true>
        <<<tileBlocks, 256>>>(nullptr, nullptr, W2, b2, N);

    // propagate 2
    gather_kernel<<<gatherBlocks, 256>>>(N);

    // out = (dinv*S) @ W_out + b_out  (fp32)
    gemm_tiled<BUF_S, BUF_EXT, true, false, false>
        <<<tileBlocks, 256>>>(nullptr, out, W_out, b_out, N);
}

// round 15
// speedup vs baseline: 1.3386x; 1.1805x over previous
#include <cuda_runtime.h>
#include <cuda_fp16.h>

#define NMAX 100000
#define HDIM 64
#define SLOTS 128     // max degree safety: Poisson(32) max over 100k nodes ~58

// ---- device scratch (no allocations allowed), 16B-aligned ----
__device__ __align__(16) int     d_cnt [NMAX];
__device__ __align__(16) int     d_adj [(size_t)NMAX * SLOTS];  // padded adjacency
__device__ __align__(16) float   d_dinv[NMAX];
// +1 row: dummy zero node (index NMAX) used for tail padding
__device__ __align__(16) __half2 d_gh[(size_t)(NMAX + 1) * (HDIM / 2)];
__device__ __align__(16) float   d_S [(size_t)NMAX * HDIM];     // propagate result (fp32)

#define BUF_EXT 0
#define BUF_S   1

// ---- packed f32x2 helpers (FFMA2, used by gemm_tiled B/C) ----
typedef unsigned long long ull;
__device__ __forceinline__ ull pack2(float lo, float hi) {
    ull r; asm("mov.b64 %0, {%1, %2};" : "=l"(r) : "f"(lo), "f"(hi)); return r;
}
__device__ __forceinline__ ull dup2(float v) {
    ull r; asm("mov.b64 %0, {%1, %1};" : "=l"(r) : "f"(v)); return r;
}
__device__ __forceinline__ void unpack2(ull v, float& lo, float& hi) {
    asm("mov.b64 {%0, %1}, %2;" : "=f"(lo), "=f"(hi) : "l"(v));
}
__device__ __forceinline__ void fma2(ull& d, ull a, ull b) {
    asm("fma.rn.f32x2 %0, %1, %2, %3;" : "=l"(d) : "l"(a), "l"(b), "l"(d));
}
__device__ __forceinline__ __half2 u2h2(unsigned int u) {
    __half2 h; *(unsigned int*)&h = u; return h;
}

// ---- tensor-core helpers (mma.sync m16n8k16 f16 -> f32) ----
__device__ __forceinline__ unsigned smem_u32p(const void* p) {
    return (unsigned)__cvta_generic_to_shared(p);
}
__device__ __forceinline__ void ldm_x4(unsigned& r0, unsigned& r1,
                                       unsigned& r2, unsigned& r3, unsigned addr) {
    asm volatile("ldmatrix.sync.aligned.m8n8.x4.shared.b16 {%0,%1,%2,%3}, [%4];"
                 : "=r"(r0), "=r"(r1), "=r"(r2), "=r"(r3) : "r"(addr));
}
__device__ __forceinline__ void ldm_x4_t(unsigned& r0, unsigned& r1,
                                         unsigned& r2, unsigned& r3, unsigned addr) {
    asm volatile("ldmatrix.sync.aligned.m8n8.x4.trans.shared.b16 {%0,%1,%2,%3}, [%4];"
                 : "=r"(r0), "=r"(r1), "=r"(r2), "=r"(r3) : "r"(addr));
}
__device__ __forceinline__ void mma16816(float c[4],
                                         unsigned a0, unsigned a1, unsigned a2, unsigned a3,
                                         unsigned b0, unsigned b1) {
    asm volatile("mma.sync.aligned.m16n8k16.row.col.f32.f16.f16.f32 "
                 "{%0,%1,%2,%3}, {%4,%5,%6,%7}, {%8,%9}, {%0,%1,%2,%3};"
                 : "+f"(c[0]), "+f"(c[1]), "+f"(c[2]), "+f"(c[3])
                 : "r"(a0), "r"(a1), "r"(a2), "r"(a3), "r"(b0), "r"(b1));
}

// One m16 x n64 x k16 MMA step. A: smem half [m][PA], rows mbase..+15, k off ka.
// W: smem half [k][PW] (k-major), rows kw..kw+15, 64 cols. 8 n-blocks -> acc[8][4].
template<int PA, int PW>
__device__ __forceinline__ void mma_k16(float acc[8][4], const __half* A, int mbase, int ka,
                                        const __half* Wt, int kw, int lane) {
    unsigned a0, a1, a2, a3;
    int arow = mbase + (lane & 15);
    int acol = ka + ((lane >> 4) << 3);
    ldm_x4(a0, a1, a2, a3, smem_u32p(&A[arow * PA + acol]));
    int q = lane >> 3;            // quarter-warp
    int lr = lane & 7;
    int krow = kw + lr + ((q & 1) << 3);
#pragma unroll
    for (int nb2 = 0; nb2 < 4; nb2++) {
        int ncol = (nb2 << 4) + ((q >> 1) << 3);
        unsigned b0, b1, b2, b3;
        ldm_x4_t(b0, b1, b2, b3, smem_u32p(&Wt[krow * PW + ncol]));
        mma16816(acc[2 * nb2],     a0, a1, a2, a3, b0, b1);
        mma16816(acc[2 * nb2 + 1], a0, a1, a2, a3, b2, b3);
    }
}

// ------------------------------------------------------------------
// adjacency build (edge_index is int32: JAX x64 disabled)
// ------------------------------------------------------------------
__global__ void zero_cnt_kernel(int n) {
    int i = blockIdx.x * blockDim.x + threadIdx.x;
    if (i < n) d_cnt[i] = 0;
    if (i < 32)
        ((unsigned int*)&d_gh[(size_t)NMAX * 32])[i] = 0u;
}

__global__ void fill_adj_kernel(const int* __restrict__ e0,
                                const int* __restrict__ e1, int E) {
    int e = blockIdx.x * blockDim.x + threadIdx.x;
    if (e >= E) return;
    int u = __ldg(&e0[e]);
    int v = __ldg(&e1[e]);
    int pu = atomicAdd(&d_cnt[u], 1);
    if (pu < SLOTS) d_adj[(size_t)u * SLOTS + pu] = v;
    int pv = atomicAdd(&d_cnt[v], 1);
    if (pv < SLOTS) d_adj[(size_t)v * SLOTS + pv] = u;
}

__global__ void pad_adj_kernel(int nn) {
    int i = blockIdx.x * blockDim.x + threadIdx.x;
    if (i >= nn) return;
    int c = min(d_cnt[i], SLOTS);
    int r = min((c + 7) & ~7, SLOTS);
    for (int t = c; t < r; t++) d_adj[(size_t)i * SLOTS + t] = NMAX;
}

// ------------------------------------------------------------------
// propagate (gather-only): S[i] = sum_{j in adj[i]} g[j]   (unchanged)
// ------------------------------------------------------------------
__global__ __launch_bounds__(256)
void gather_kernel(int nn) {
    int node = blockIdx.x * 8 + (threadIdx.x >> 5);
    int lane = threadIdx.x & 31;
    if (node >= nn) return;
    int w = lane >> 4;
    int c = lane & 15;
    int cnt = min(d_cnt[node], SLOTS);
    int cntp = min((cnt + 7) & ~7, SLOTS);
    const int* adj = &d_adj[(size_t)node * SLOTS];
    const uint2* gh2 = (const uint2*)d_gh;

    float4 facc = make_float4(0.f, 0.f, 0.f, 0.f);

    int4 nb = make_int4(NMAX, NMAX, NMAX, NMAX);
    if (cntp > 0) nb = __ldg((const int4*)&adj[4 * w]);
    for (int j = 0; j < cntp; j += 8) {
        int4 cur = nb;
        if (j + 8 < cntp)
            nb = __ldg((const int4*)&adj[j + 8 + 4 * w]);
        uint2 v0 = __ldg(&gh2[(size_t)cur.x * 16 + c]);
        uint2 v1 = __ldg(&gh2[(size_t)cur.y * 16 + c]);
        uint2 v2 = __ldg(&gh2[(size_t)cur.z * 16 + c]);
        uint2 v3 = __ldg(&gh2[(size_t)cur.w * 16 + c]);
        __half2 h0 = __hadd2(__hadd2(u2h2(v0.x), u2h2(v1.x)),
                             __hadd2(u2h2(v2.x), u2h2(v3.x)));
        __half2 h1 = __hadd2(__hadd2(u2h2(v0.y), u2h2(v1.y)),
                             __hadd2(u2h2(v2.y), u2h2(v3.y)));
        float2 f0 = __half22float2(h0);
        float2 f1 = __half22float2(h1);
        facc.x += f0.x; facc.y += f0.y; facc.z += f1.x; facc.w += f1.y;
    }
    facc.x += __shfl_xor_sync(0xffffffffu, facc.x, 16);
    facc.y += __shfl_xor_sync(0xffffffffu, facc.y, 16);
    facc.z += __shfl_xor_sync(0xffffffffu, facc.z, 16);
    facc.w += __shfl_xor_sync(0xffffffffu, facc.w, 16);
    if (w == 0)
        ((float4*)d_S)[(size_t)node * 16 + c] = facc;
}

// ==================================================================
// gemmA (fused, TENSOR-CORE): h = x@W_in+b_in; g = dinv*relu(h@W1+b1) -> d_gh
// fp16 inputs, fp32 mma accumulation. Warp = 16 nodes x 64 cols.
// smem reuse: sU1 = Wt_in (ph1) -> Hs (ph2); sU2 = A chunks (ph1) -> Wt1 (ph2).
// ==================================================================
#define AP1 40   // phase-1 A tile pitch (halves): 32 k + 8 pad; row 80 B (16B mult)
#define HP1 72   // Hs / Wt pitch (halves): 64 + 8 pad; row 144 B (16B mult)

__global__ __launch_bounds__(256, 2)
void gemm_fused_A(const float* __restrict__ x,
                  const float* __restrict__ W_in, const float* __restrict__ b_in,
                  const float* __restrict__ W1,   const float* __restrict__ b1,
                  int nn) {
    __shared__ __align__(16) __half sU1[128 * HP1];  // 18.4 KB
    __shared__ __align__(16) __half sU2[128 * AP1];  // 10.2 KB
    __shared__ float sB[128];                        // b_in | b1

    int tid = threadIdx.x;
    int warp = tid >> 5, lane = tid & 31;
    int m0 = blockIdx.x * 128;
    int mbase = warp * 16;

    // ---- load W_in (128x64 f32) -> sU1 half [k][HP1]; biases -> sB ----
#pragma unroll
    for (int l = 0; l < 8; l++) {
        int fi = tid + l * 256;            // 2048 float4 = 8192 floats
        int k = fi >> 4;
        int n4 = (fi & 15) * 4;
        float4 w4 = __ldg((const float4*)(W_in + (size_t)k * 64 + n4));
        __half2 h0 = __floats2half2_rn(w4.x, w4.y);
        __half2 h1 = __floats2half2_rn(w4.z, w4.w);
        uint2 pk; pk.x = *(unsigned*)&h0; pk.y = *(unsigned*)&h1;
        *(uint2*)&sU1[k * HP1 + n4] = pk;
    }
    if (tid < 64)       sB[tid] = __ldg(b_in + tid);
    else if (tid < 128) sB[tid] = __ldg(b1 + tid - 64);

    // ---- phase 1: h = x @ W_in  (bias added at store) ----
    float acc[8][4];
#pragma unroll
    for (int i = 0; i < 8; i++)
#pragma unroll
        for (int j = 0; j < 4; j++) acc[i][j] = 0.f;

    float4 xr[4];
#pragma unroll
    for (int l = 0; l < 4; l++) {          // prefetch chunk 0 (kc=0)
        int fi = tid + l * 256;            // 1024 f4: node = fi>>3, q = fi&7
        int node = fi >> 3, q = fi & 7;
        int gm = m0 + node;
        xr[l] = (gm < nn) ? __ldg((const float4*)(x + (size_t)gm * 128 + 4 * q))
                          : make_float4(0.f, 0.f, 0.f, 0.f);
    }
#pragma unroll
    for (int kc = 0; kc < 128; kc += 32) {
        __syncthreads();                   // also orders W_in/bias loads (kc=0)
#pragma unroll
        for (int l = 0; l < 4; l++) {      // cvt + STS chunk
            int fi = tid + l * 256;
            int node = fi >> 3, q = fi & 7;
            __half2 h0 = __floats2half2_rn(xr[l].x, xr[l].y);
            __half2 h1 = __floats2half2_rn(xr[l].z, xr[l].w);
            uint2 pk; pk.x = *(unsigned*)&h0; pk.y = *(unsigned*)&h1;
            *(uint2*)&sU2[node * AP1 + 4 * q] = pk;
        }
        __syncthreads();
        if (kc + 32 < 128) {               // prefetch next chunk
#pragma unroll
            for (int l = 0; l < 4; l++) {
                int fi = tid + l * 256;
                int node = fi >> 3, q = fi & 7;
                int gm = m0 + node;
                xr[l] = (gm < nn)
                    ? __ldg((const float4*)(x + (size_t)gm * 128 + kc + 32 + 4 * q))
                    : make_float4(0.f, 0.f, 0.f, 0.f);
            }
        }
        mma_k16<AP1, HP1>(acc, sU2, mbase, 0,  sU1, kc,      lane);
        mma_k16<AP1, HP1>(acc, sU2, mbase, 16, sU1, kc + 16, lane);
    }
    __syncthreads();                       // all phase-1 mma reads done

    // ---- transition: Hs (h+bias, half) overlays sU1; W1 -> sU2 ----
    int g = lane >> 2, t = lane & 3;
#pragma unroll
    for (int nb = 0; nb < 8; nb++) {
        int n0 = nb * 8 + 2 * t;
        float bx = sB[n0], by = sB[n0 + 1];
        *(__half2*)&sU1[(mbase + g) * HP1 + n0] =
            __floats2half2_rn(acc[nb][0] + bx, acc[nb][1] + by);
        *(__half2*)&sU1[(mbase + g + 8) * HP1 + n0] =
            __floats2half2_rn(acc[nb][2] + bx, acc[nb][3] + by);
    }
#pragma unroll
    for (int l = 0; l < 4; l++) {          // W1 (64x64) -> sU2 half [k][HP1]
        int fi = tid + l * 256;            // 1024 f4 = 4096 floats
        int k = fi >> 4;
        int n4 = (fi & 15) * 4;
        float4 w4 = __ldg((const float4*)(W1 + (size_t)k * 64 + n4));
        __half2 h0 = __floats2half2_rn(w4.x, w4.y);
        __half2 h1 = __floats2half2_rn(w4.z, w4.w);
        uint2 pk; pk.x = *(unsigned*)&h0; pk.y = *(unsigned*)&h1;
        *(uint2*)&sU2[k * HP1 + n4] = pk;
    }
    __syncthreads();

    // ---- phase 2: g = dinv * relu(h @ W1 + b1) ----
    float acc2[8][4];
#pragma unroll
    for (int i = 0; i < 8; i++)
#pragma unroll
        for (int j = 0; j < 4; j++) acc2[i][j] = 0.f;
#pragma unroll
    for (int k16 = 0; k16 < 64; k16 += 16)
        mma_k16<HP1, HP1>(acc2, sU1, mbase, k16, sU2, k16, lane);

    // ---- epilogue: dinv, +b1, relu, *dinv, store fp16 g ----
    int r1 = mbase + g, r2 = r1 + 8;
    int gm1 = m0 + r1, gm2 = m0 + r2;
    float dv1 = 0.f, dv2 = 0.f;
    if (gm1 < nn) {
        int c = d_cnt[gm1];
        dv1 = c > 0 ? rsqrtf((float)c) : 0.f;
        if (t == 0) d_dinv[gm1] = dv1;
    }
    if (gm2 < nn) {
        int c = d_cnt[gm2];
        dv2 = c > 0 ? rsqrtf((float)c) : 0.f;
        if (t == 0) d_dinv[gm2] = dv2;
    }
#pragma unroll
    for (int nb = 0; nb < 8; nb++) {
        int n0 = nb * 8 + 2 * t;
        float bx = sB[64 + n0], by = sB[64 + n0 + 1];
        if (gm1 < nn) {
            float v0 = fmaxf(acc2[nb][0] + bx, 0.f) * dv1;
            float v1 = fmaxf(acc2[nb][1] + by, 0.f) * dv1;
            d_gh[(size_t)gm1 * 32 + (n0 >> 1)] = __floats2half2_rn(v0, v1);
        }
        if (gm2 < nn) {
            float v0 = fmaxf(acc2[nb][2] + bx, 0.f) * dv2;
            float v1 = fmaxf(acc2[nb][3] + by, 0.f) * dv2;
            d_gh[(size_t)gm2 * 32 + (n0 >> 1)] = __floats2half2_rn(v0, v1);
        }
    }
}

// ==================================================================
// FFMA2 tiled GEMM (unchanged): gemmB / gemmC
// ==================================================================
#define MT 128
#define KC 32
#define AS_PITCH 132

__device__ __forceinline__ void ldg_w(float4 wr[2], const float* W, int kc, int tid) {
#pragma unroll
    for (int l = 0; l < 2; l++) {
        int idx = tid + l * 256;
        int k = idx >> 4, c4 = idx & 15;
        wr[l] = __ldg((const float4*)(W + (size_t)(kc + k) * HDIM + 4 * c4));
    }
}
__device__ __forceinline__ void sts_w(const float4 wr[2], float* sWs, int tid) {
#pragma unroll
    for (int l = 0; l < 2; l++) {
        int idx = tid + l * 256;
        int k = idx >> 4, c4 = idx & 15;
        *(float4*)&sWs[k * HDIM + 4 * c4] = wr[l];
    }
}
template<int KP, bool SCALE_IN>
__device__ __forceinline__ void ldg_a(float4 ar[4], const float* in,
                                      int m0, int kc, int tid, int nn) {
#pragma unroll
    for (int l = 0; l < 4; l++) {
        int idx = tid + l * 256;
        int node = idx >> 3, kq = idx & 7;
        int gm = m0 + node;
        float4 av = make_float4(0.f, 0.f, 0.f, 0.f);
        if (gm < nn) {
            av = __ldg((const float4*)(in + (size_t)gm * KP + kc + 4 * kq));
            if (SCALE_IN) {
                float dv = d_dinv[gm];
                av.x *= dv; av.y *= dv; av.z *= dv; av.w *= dv;
            }
        }
        ar[l] = av;
    }
}
__device__ __forceinline__ void sts_a(const float4 ar[4], float* sAs, int tid) {
#pragma unroll
    for (int l = 0; l < 4; l++) {
        int idx = tid + l * 256;
        int node = idx >> 3, kq = idx & 7;
        sAs[(4 * kq + 0) * AS_PITCH + node] = ar[l].x;
        sAs[(4 * kq + 1) * AS_PITCH + node] = ar[l].y;
        sAs[(4 * kq + 2) * AS_PITCH + node] = ar[l].z;
        sAs[(4 * kq + 3) * AS_PITCH + node] = ar[l].w;
    }
}
__device__ __forceinline__ void mma_chunk(ull acc[4][4], const float* sAs,
                                          const float* sWs, int tx, int ty) {
#pragma unroll
    for (int k = 0; k < KC; k++) {
        ulonglong2 a01 = *(const ulonglong2*)&sAs[k * AS_PITCH + 8 * ty];
        ulonglong2 a23 = *(const ulonglong2*)&sAs[k * AS_PITCH + 8 * ty + 4];
        float4 wv = *(const float4*)&sWs[k * HDIM + 4 * tx];
        ull w0 = dup2(wv.x), w1 = dup2(wv.y), w2 = dup2(wv.z), w3 = dup2(wv.w);
        fma2(acc[0][0], a01.x, w0); fma2(acc[0][1], a01.x, w1);
        fma2(acc[0][2], a01.x, w2); fma2(acc[0][3], a01.x, w3);
        fma2(acc[1][0], a01.y, w0); fma2(acc[1][1], a01.y, w1);
        fma2(acc[1][2], a01.y, w2); fma2(acc[1][3], a01.y, w3);
        fma2(acc[2][0], a23.x, w0); fma2(acc[2][1], a23.x, w1);
        fma2(acc[2][2], a23.x, w2); fma2(acc[2][3], a23.x, w3);
        fma2(acc[3][0], a23.y, w0); fma2(acc[3][1], a23.y, w1);
        fma2(acc[3][2], a23.y, w2); fma2(acc[3][3], a23.y, w3);
    }
}
__device__ __forceinline__ void store_g_half(int gm, int tx, float4 r) {
    __half2 h0 = __floats2half2_rn(r.x, r.y);
    __half2 h1 = __floats2half2_rn(r.z, r.w);
    uint2 pk;
    pk.x = *(unsigned int*)&h0;
    pk.y = *(unsigned int*)&h1;
    *(uint2*)&d_gh[(size_t)gm * 32 + 2 * tx] = pk;
}

template<int IN_SRC, int OUT_DST, bool SCALE_IN, bool RELU, bool SCALE_OUT>
__global__ __launch_bounds__(256, 2)
void gemm_tiled(const float* __restrict__ ext_in, float* __restrict__ ext_out,
                const float* __restrict__ W, const float* __restrict__ bias, int nn) {
    __shared__ __align__(16) float As[KC * AS_PITCH];
    __shared__ __align__(16) float Ws[KC * HDIM];

    int tid = threadIdx.x;
    int tx = tid & 15, ty = tid >> 4;
    int m0 = blockIdx.x * MT;

    const float* in = (IN_SRC == BUF_EXT) ? ext_in : d_S;

    ull acc[4][4];
    {
        float4 b4 = __ldg((const float4*)(bias + 4 * tx));
#pragma unroll
        for (int p = 0; p < 4; p++) {
            acc[p][0] = dup2(b4.x); acc[p][1] = dup2(b4.y);
            acc[p][2] = dup2(b4.z); acc[p][3] = dup2(b4.w);
        }
    }
    float4 ar[4], wr[2];
    ldg_a<HDIM, SCALE_IN>(ar, in, m0, 0, tid, nn);
    ldg_w(wr, W, 0, tid);
#pragma unroll
    for (int kc = 0; kc < HDIM; kc += KC) {
        __syncthreads();
        sts_a(ar, As, tid);
        sts_w(wr, Ws, tid);
        __syncthreads();
        if (kc + KC < HDIM) {
            ldg_a<HDIM, SCALE_IN>(ar, in, m0, kc + KC, tid, nn);
            ldg_w(wr, W, kc + KC, tid);
        }
        mma_chunk(acc, As, Ws, tx, ty);
    }

#pragma unroll
    for (int p = 0; p < 4; p++) {
        float4 re, ro;
        unpack2(acc[p][0], re.x, ro.x);
        unpack2(acc[p][1], re.y, ro.y);
        unpack2(acc[p][2], re.z, ro.z);
        unpack2(acc[p][3], re.w, ro.w);
        int ge = m0 + 8 * ty + 2 * p;
        int go = ge + 1;
        if (RELU) {
            re.x = fmaxf(re.x, 0.f); re.y = fmaxf(re.y, 0.f);
            re.z = fmaxf(re.z, 0.f); re.w = fmaxf(re.w, 0.f);
            ro.x = fmaxf(ro.x, 0.f); ro.y = fmaxf(ro.y, 0.f);
            ro.z = fmaxf(ro.z, 0.f); ro.w = fmaxf(ro.w, 0.f);
        }
        if (ge < nn) {
            if (SCALE_OUT) {
                float dv = d_dinv[ge];
                re.x *= dv; re.y *= dv; re.z *= dv; re.w *= dv;
            }
            if (OUT_DST == BUF_S) store_g_half(ge, tx, re);
            else *(float4*)&ext_out[(size_t)ge * HDIM + 4 * tx] = re;
        }
        if (go < nn) {
            if (SCALE_OUT) {
                float dv = d_dinv[go];
                ro.x *= dv; ro.y *= dv; ro.z *= dv; ro.w *= dv;
            }
            if (OUT_DST == BUF_S) store_g_half(go, tx, ro);
            else *(float4*)&ext_out[(size_t)go * HDIM + 4 * tx] = ro;
        }
    }
}

// ------------------------------------------------------------------
// launch: 0 zero  1 fill  2 pad  3 gemmA(profiled)  4 gather1  5 gemmB
//         6 gather2  7 gemmC
// ------------------------------------------------------------------
extern "C" void kernel_launch(void* const* d_in, const int* in_sizes, int n_in,
                              void* d_out, int out_size) {
    const float* x     = (const float*)d_in[0];
    const int*   ei    = (const int*)d_in[1];     // int32 edge indices
    const float* W_in  = (const float*)d_in[2];
    const float* b_in  = (const float*)d_in[3];
    const float* W1    = (const float*)d_in[4];
    const float* b1    = (const float*)d_in[5];
    const float* W2    = (const float*)d_in[6];
    const float* b2    = (const float*)d_in[7];
    const float* W_out = (const float*)d_in[8];
    const float* b_out = (const float*)d_in[9];
    float* out = (float*)d_out;

    int N = in_sizes[0] / 128;   // 100000
    int E = in_sizes[1] / 2;     // 1600000
    const int* e0 = ei;
    const int* e1 = ei + E;

    int tileBlocks = (N + MT - 1) / MT;
    int gatherBlocks = (N + 7) / 8;

    zero_cnt_kernel<<<(N + 255) / 256, 256>>>(N);
    fill_adj_kernel<<<(E + 255) / 256, 256>>>(e0, e1, E);
    pad_adj_kernel<<<(N + 255) / 256, 256>>>(N);

    // fused tensor-core: h = x@W_in+b_in; g = dinv*relu(h@W1+b1) -> fp16; dinv
    gemm_fused_A<<<tileBlocks, 256>>>(x, W_in, b_in, W1, b1, N);

    // propagate 1
    gather_kernel<<<gatherBlocks, 256>>>(N);

    // g = dinv * relu((dinv*S)@W2 + b2) -> d_gh (fp16)
    gemm_tiled<BUF_S, BUF_S, true, true, true>
        <<<tileBlocks, 256>>>(nullptr, nullptr, W2, b2, N);

    // propagate 2
    gather_kernel<<<gatherBlocks, 256>>>(N);

    // out = (dinv*S) @ W_out + b_out  (fp32, FFMA2 — correctness anchor)
    gemm_tiled<BUF_S, BUF_EXT, true, false, false>
        <<<tileBlocks, 256>>>(nullptr, out, W_out, b_out, N);
}

// round 16
// speedup vs baseline: 1.5433x; 1.1529x over previous
#include <cuda_runtime.h>
#include <cuda_fp16.h>

#define NMAX 100000
#define HDIM 64
#define SLOTS 128     // max degree safety: Poisson(32) max over 100k nodes ~58

// ---- device scratch (no allocations allowed), 16B-aligned ----
__device__ __align__(16) int     d_cnt [NMAX];
__device__ __align__(16) int     d_adj [(size_t)NMAX * SLOTS];  // padded adjacency
__device__ __align__(16) float   d_dinv[NMAX];
// +1 row: dummy zero node (index NMAX) used for tail padding
__device__ __align__(16) __half2 d_gh[(size_t)(NMAX + 1) * (HDIM / 2)];
__device__ __align__(16) float   d_S [(size_t)NMAX * HDIM];     // propagate result (fp32)

#define BUF_EXT 0
#define BUF_S   1

__device__ __forceinline__ __half2 u2h2(unsigned int u) {
    __half2 h; *(unsigned int*)&h = u; return h;
}

// ---- tensor-core helpers (mma.sync m16n8k16 f16 -> f32) ----
__device__ __forceinline__ unsigned smem_u32p(const void* p) {
    return (unsigned)__cvta_generic_to_shared(p);
}
__device__ __forceinline__ void ldm_x4(unsigned& r0, unsigned& r1,
                                       unsigned& r2, unsigned& r3, unsigned addr) {
    asm volatile("ldmatrix.sync.aligned.m8n8.x4.shared.b16 {%0,%1,%2,%3}, [%4];"
                 : "=r"(r0), "=r"(r1), "=r"(r2), "=r"(r3) : "r"(addr));
}
__device__ __forceinline__ void ldm_x4_t(unsigned& r0, unsigned& r1,
                                         unsigned& r2, unsigned& r3, unsigned addr) {
    asm volatile("ldmatrix.sync.aligned.m8n8.x4.trans.shared.b16 {%0,%1,%2,%3}, [%4];"
                 : "=r"(r0), "=r"(r1), "=r"(r2), "=r"(r3) : "r"(addr));
}
__device__ __forceinline__ void mma16816(float c[4],
                                         unsigned a0, unsigned a1, unsigned a2, unsigned a3,
                                         unsigned b0, unsigned b1) {
    asm volatile("mma.sync.aligned.m16n8k16.row.col.f32.f16.f16.f32 "
                 "{%0,%1,%2,%3}, {%4,%5,%6,%7}, {%8,%9}, {%0,%1,%2,%3};"
                 : "+f"(c[0]), "+f"(c[1]), "+f"(c[2]), "+f"(c[3])
                 : "r"(a0), "r"(a1), "r"(a2), "r"(a3), "r"(b0), "r"(b1));
}

// One m16 x n64 x k16 MMA step. A: smem half [m][PA], rows mbase..+15, k off ka.
// W: smem half [k][PW] (k-major), rows kw..kw+15, 64 cols. 8 n-blocks -> acc[8][4].
template<int PA, int PW>
__device__ __forceinline__ void mma_k16(float acc[8][4], const __half* A, int mbase, int ka,
                                        const __half* Wt, int kw, int lane) {
    unsigned a0, a1, a2, a3;
    int arow = mbase + (lane & 15);
    int acol = ka + ((lane >> 4) << 3);
    ldm_x4(a0, a1, a2, a3, smem_u32p(&A[arow * PA + acol]));
    int q = lane >> 3;            // quarter-warp
    int lr = lane & 7;
    int krow = kw + lr + ((q & 1) << 3);
#pragma unroll
    for (int nb2 = 0; nb2 < 4; nb2++) {
        int ncol = (nb2 << 4) + ((q >> 1) << 3);
        unsigned b0, b1, b2, b3;
        ldm_x4_t(b0, b1, b2, b3, smem_u32p(&Wt[krow * PW + ncol]));
        mma16816(acc[2 * nb2],     a0, a1, a2, a3, b0, b1);
        mma16816(acc[2 * nb2 + 1], a0, a1, a2, a3, b2, b3);
    }
}

// ------------------------------------------------------------------
// adjacency build (edge_index is int32: JAX x64 disabled)
// ------------------------------------------------------------------
__global__ void zero_cnt_kernel(int n) {
    int i = blockIdx.x * blockDim.x + threadIdx.x;
    if (i < n) d_cnt[i] = 0;
    if (i < 32)
        ((unsigned int*)&d_gh[(size_t)NMAX * 32])[i] = 0u;
}

__global__ void fill_adj_kernel(const int* __restrict__ e0,
                                const int* __restrict__ e1, int E) {
    int e = blockIdx.x * blockDim.x + threadIdx.x;
    if (e >= E) return;
    int u = __ldg(&e0[e]);
    int v = __ldg(&e1[e]);
    int pu = atomicAdd(&d_cnt[u], 1);
    if (pu < SLOTS) d_adj[(size_t)u * SLOTS + pu] = v;
    int pv = atomicAdd(&d_cnt[v], 1);
    if (pv < SLOTS) d_adj[(size_t)v * SLOTS + pv] = u;
}

__global__ void pad_adj_kernel(int nn) {
    int i = blockIdx.x * blockDim.x + threadIdx.x;
    if (i >= nn) return;
    int c = min(d_cnt[i], SLOTS);
    int r = min((c + 7) & ~7, SLOTS);
    for (int t = c; t < r; t++) d_adj[(size_t)i * SLOTS + t] = NMAX;
}

// ------------------------------------------------------------------
// propagate (gather-only): S[i] = sum_{j in adj[i]} g[j]   (unchanged)
// ------------------------------------------------------------------
__global__ __launch_bounds__(256)
void gather_kernel(int nn) {
    int node = blockIdx.x * 8 + (threadIdx.x >> 5);
    int lane = threadIdx.x & 31;
    if (node >= nn) return;
    int w = lane >> 4;
    int c = lane & 15;
    int cnt = min(d_cnt[node], SLOTS);
    int cntp = min((cnt + 7) & ~7, SLOTS);
    const int* adj = &d_adj[(size_t)node * SLOTS];
    const uint2* gh2 = (const uint2*)d_gh;

    float4 facc = make_float4(0.f, 0.f, 0.f, 0.f);

    int4 nb = make_int4(NMAX, NMAX, NMAX, NMAX);
    if (cntp > 0) nb = __ldg((const int4*)&adj[4 * w]);
    for (int j = 0; j < cntp; j += 8) {
        int4 cur = nb;
        if (j + 8 < cntp)
            nb = __ldg((const int4*)&adj[j + 8 + 4 * w]);
        uint2 v0 = __ldg(&gh2[(size_t)cur.x * 16 + c]);
        uint2 v1 = __ldg(&gh2[(size_t)cur.y * 16 + c]);
        uint2 v2 = __ldg(&gh2[(size_t)cur.z * 16 + c]);
        uint2 v3 = __ldg(&gh2[(size_t)cur.w * 16 + c]);
        __half2 h0 = __hadd2(__hadd2(u2h2(v0.x), u2h2(v1.x)),
                             __hadd2(u2h2(v2.x), u2h2(v3.x)));
        __half2 h1 = __hadd2(__hadd2(u2h2(v0.y), u2h2(v1.y)),
                             __hadd2(u2h2(v2.y), u2h2(v3.y)));
        float2 f0 = __half22float2(h0);
        float2 f1 = __half22float2(h1);
        facc.x += f0.x; facc.y += f0.y; facc.z += f1.x; facc.w += f1.y;
    }
    facc.x += __shfl_xor_sync(0xffffffffu, facc.x, 16);
    facc.y += __shfl_xor_sync(0xffffffffu, facc.y, 16);
    facc.z += __shfl_xor_sync(0xffffffffu, facc.z, 16);
    facc.w += __shfl_xor_sync(0xffffffffu, facc.w, 16);
    if (w == 0)
        ((float4*)d_S)[(size_t)node * 16 + c] = facc;
}

// ==================================================================
// gemmA (fused, TENSOR-CORE): h = x@W_in+b_in; g = dinv*relu(h@W1+b1) -> d_gh
// ==================================================================
#define AP1 40   // phase-1 A tile pitch (halves)
#define HP1 72   // Hs / Wt / A pitch (halves): 64 + 8 pad; row 144 B

__global__ __launch_bounds__(256, 2)
void gemm_fused_A(const float* __restrict__ x,
                  const float* __restrict__ W_in, const float* __restrict__ b_in,
                  const float* __restrict__ W1,   const float* __restrict__ b1,
                  int nn) {
    __shared__ __align__(16) __half sU1[128 * HP1];  // 18.4 KB
    __shared__ __align__(16) __half sU2[128 * AP1];  // 10.2 KB
    __shared__ float sB[128];                        // b_in | b1

    int tid = threadIdx.x;
    int warp = tid >> 5, lane = tid & 31;
    int m0 = blockIdx.x * 128;
    int mbase = warp * 16;

    // ---- load W_in (128x64 f32) -> sU1 half [k][HP1]; biases -> sB ----
#pragma unroll
    for (int l = 0; l < 8; l++) {
        int fi = tid + l * 256;
        int k = fi >> 4;
        int n4 = (fi & 15) * 4;
        float4 w4 = __ldg((const float4*)(W_in + (size_t)k * 64 + n4));
        __half2 h0 = __floats2half2_rn(w4.x, w4.y);
        __half2 h1 = __floats2half2_rn(w4.z, w4.w);
        uint2 pk; pk.x = *(unsigned*)&h0; pk.y = *(unsigned*)&h1;
        *(uint2*)&sU1[k * HP1 + n4] = pk;
    }
    if (tid < 64)       sB[tid] = __ldg(b_in + tid);
    else if (tid < 128) sB[tid] = __ldg(b1 + tid - 64);

    // ---- phase 1: h = x @ W_in ----
    float acc[8][4];
#pragma unroll
    for (int i = 0; i < 8; i++)
#pragma unroll
        for (int j = 0; j < 4; j++) acc[i][j] = 0.f;

    float4 xr[4];
#pragma unroll
    for (int l = 0; l < 4; l++) {
        int fi = tid + l * 256;
        int node = fi >> 3, q = fi & 7;
        int gm = m0 + node;
        xr[l] = (gm < nn) ? __ldg((const float4*)(x + (size_t)gm * 128 + 4 * q))
                          : make_float4(0.f, 0.f, 0.f, 0.f);
    }
#pragma unroll
    for (int kc = 0; kc < 128; kc += 32) {
        __syncthreads();
#pragma unroll
        for (int l = 0; l < 4; l++) {
            int fi = tid + l * 256;
            int node = fi >> 3, q = fi & 7;
            __half2 h0 = __floats2half2_rn(xr[l].x, xr[l].y);
            __half2 h1 = __floats2half2_rn(xr[l].z, xr[l].w);
            uint2 pk; pk.x = *(unsigned*)&h0; pk.y = *(unsigned*)&h1;
            *(uint2*)&sU2[node * AP1 + 4 * q] = pk;
        }
        __syncthreads();
        if (kc + 32 < 128) {
#pragma unroll
            for (int l = 0; l < 4; l++) {
                int fi = tid + l * 256;
                int node = fi >> 3, q = fi & 7;
                int gm = m0 + node;
                xr[l] = (gm < nn)
                    ? __ldg((const float4*)(x + (size_t)gm * 128 + kc + 32 + 4 * q))
                    : make_float4(0.f, 0.f, 0.f, 0.f);
            }
        }
        mma_k16<AP1, HP1>(acc, sU2, mbase, 0,  sU1, kc,      lane);
        mma_k16<AP1, HP1>(acc, sU2, mbase, 16, sU1, kc + 16, lane);
    }
    __syncthreads();

    // ---- transition: Hs overlays sU1; W1 -> sU2 ----
    int g = lane >> 2, t = lane & 3;
#pragma unroll
    for (int nb = 0; nb < 8; nb++) {
        int n0 = nb * 8 + 2 * t;
        float bx = sB[n0], by = sB[n0 + 1];
        *(__half2*)&sU1[(mbase + g) * HP1 + n0] =
            __floats2half2_rn(acc[nb][0] + bx, acc[nb][1] + by);
        *(__half2*)&sU1[(mbase + g + 8) * HP1 + n0] =
            __floats2half2_rn(acc[nb][2] + bx, acc[nb][3] + by);
    }
#pragma unroll
    for (int l = 0; l < 4; l++) {
        int fi = tid + l * 256;
        int k = fi >> 4;
        int n4 = (fi & 15) * 4;
        float4 w4 = __ldg((const float4*)(W1 + (size_t)k * 64 + n4));
        __half2 h0 = __floats2half2_rn(w4.x, w4.y);
        __half2 h1 = __floats2half2_rn(w4.z, w4.w);
        uint2 pk; pk.x = *(unsigned*)&h0; pk.y = *(unsigned*)&h1;
        *(uint2*)&sU2[k * HP1 + n4] = pk;
    }
    __syncthreads();

    // ---- phase 2: g = dinv * relu(h @ W1 + b1) ----
    float acc2[8][4];
#pragma unroll
    for (int i = 0; i < 8; i++)
#pragma unroll
        for (int j = 0; j < 4; j++) acc2[i][j] = 0.f;
#pragma unroll
    for (int k16 = 0; k16 < 64; k16 += 16)
        mma_k16<HP1, HP1>(acc2, sU1, mbase, k16, sU2, k16, lane);

    // ---- epilogue ----
    int r1 = mbase + g, r2 = r1 + 8;
    int gm1 = m0 + r1, gm2 = m0 + r2;
    float dv1 = 0.f, dv2 = 0.f;
    if (gm1 < nn) {
        int c = d_cnt[gm1];
        dv1 = c > 0 ? rsqrtf((float)c) : 0.f;
        if (t == 0) d_dinv[gm1] = dv1;
    }
    if (gm2 < nn) {
        int c = d_cnt[gm2];
        dv2 = c > 0 ? rsqrtf((float)c) : 0.f;
        if (t == 0) d_dinv[gm2] = dv2;
    }
#pragma unroll
    for (int nb = 0; nb < 8; nb++) {
        int n0 = nb * 8 + 2 * t;
        float bx = sB[64 + n0], by = sB[64 + n0 + 1];
        if (gm1 < nn) {
            float v0 = fmaxf(acc2[nb][0] + bx, 0.f) * dv1;
            float v1 = fmaxf(acc2[nb][1] + by, 0.f) * dv1;
            d_gh[(size_t)gm1 * 32 + (n0 >> 1)] = __floats2half2_rn(v0, v1);
        }
        if (gm2 < nn) {
            float v0 = fmaxf(acc2[nb][2] + bx, 0.f) * dv2;
            float v1 = fmaxf(acc2[nb][3] + by, 0.f) * dv2;
            d_gh[(size_t)gm2 * 32 + (n0 >> 1)] = __floats2half2_rn(v0, v1);
        }
    }
}

// ==================================================================
// gemm_tc (TENSOR-CORE, K=64): out = f((dinv*S) @ W + b)
// OUT_DST==BUF_S: *dinv, relu -> d_gh fp16.  BUF_EXT: fp32 ext out.
// A = dinv-scaled S tile (fp16 in smem), W fp16 in smem, fp32 mma acc.
// ==================================================================
template<int OUT_DST, bool RELU, bool SCALE_OUT>
__global__ __launch_bounds__(256, 2)
void gemm_tc(float* __restrict__ ext_out,
             const float* __restrict__ W, const float* __restrict__ bias, int nn) {
    __shared__ __align__(16) __half sA[128 * HP1];   // 18.4 KB
    __shared__ __align__(16) __half sW[64 * HP1];    // 9.2 KB
    __shared__ float sB[64];

    int tid = threadIdx.x;
    int warp = tid >> 5, lane = tid & 31;
    int m0 = blockIdx.x * 128;
    int mbase = warp * 16;

    // load S tile (scale rows by dinv), cvt fp16 -> sA [node][HP1]
#pragma unroll
    for (int l = 0; l < 8; l++) {
        int fi = tid + l * 256;            // 2048 float4; 16 per row
        int node = fi >> 4;
        int q = fi & 15;
        int gm = m0 + node;
        float4 v = make_float4(0.f, 0.f, 0.f, 0.f);
        float dv = 0.f;
        if (gm < nn) {
            dv = d_dinv[gm];
            v = *(const float4*)&d_S[(size_t)gm * 64 + 4 * q];
        }
        __half2 h0 = __floats2half2_rn(v.x * dv, v.y * dv);
        __half2 h1 = __floats2half2_rn(v.z * dv, v.w * dv);
        uint2 pk; pk.x = *(unsigned*)&h0; pk.y = *(unsigned*)&h1;
        *(uint2*)&sA[node * HP1 + 4 * q] = pk;
    }
    // load W (64x64 f32) -> sW half [k][HP1]
#pragma unroll
    for (int l = 0; l < 4; l++) {
        int fi = tid + l * 256;
        int k = fi >> 4;
        int n4 = (fi & 15) * 4;
        float4 w4 = __ldg((const float4*)(W + (size_t)k * 64 + n4));
        __half2 h0 = __floats2half2_rn(w4.x, w4.y);
        __half2 h1 = __floats2half2_rn(w4.z, w4.w);
        uint2 pk; pk.x = *(unsigned*)&h0; pk.y = *(unsigned*)&h1;
        *(uint2*)&sW[k * HP1 + n4] = pk;
    }
    if (tid < 64) sB[tid] = __ldg(bias + tid);
    __syncthreads();

    float acc[8][4];
#pragma unroll
    for (int i = 0; i < 8; i++)
#pragma unroll
        for (int j = 0; j < 4; j++) acc[i][j] = 0.f;
#pragma unroll
    for (int k16 = 0; k16 < 64; k16 += 16)
        mma_k16<HP1, HP1>(acc, sA, mbase, k16, sW, k16, lane);

    // epilogue
    int g = lane >> 2, t = lane & 3;
    int r1 = mbase + g, r2 = r1 + 8;
    int gm1 = m0 + r1, gm2 = m0 + r2;
    float dv1 = 1.f, dv2 = 1.f;
    if (SCALE_OUT) {
        if (gm1 < nn) dv1 = d_dinv[gm1];
        if (gm2 < nn) dv2 = d_dinv[gm2];
    }
#pragma unroll
    for (int nb = 0; nb < 8; nb++) {
        int n0 = nb * 8 + 2 * t;
        float bx = sB[n0], by = sB[n0 + 1];
        if (gm1 < nn) {
            float v0 = acc[nb][0] + bx, v1 = acc[nb][1] + by;
            if (RELU) { v0 = fmaxf(v0, 0.f); v1 = fmaxf(v1, 0.f); }
            if (SCALE_OUT) { v0 *= dv1; v1 *= dv1; }
            if (OUT_DST == BUF_S)
                d_gh[(size_t)gm1 * 32 + (n0 >> 1)] = __floats2half2_rn(v0, v1);
            else
                *(float2*)&ext_out[(size_t)gm1 * 64 + n0] = make_float2(v0, v1);
        }
        if (gm2 < nn) {
            float v0 = acc[nb][2] + bx, v1 = acc[nb][3] + by;
            if (RELU) { v0 = fmaxf(v0, 0.f); v1 = fmaxf(v1, 0.f); }
            if (SCALE_OUT) { v0 *= dv2; v1 *= dv2; }
            if (OUT_DST == BUF_S)
                d_gh[(size_t)gm2 * 32 + (n0 >> 1)] = __floats2half2_rn(v0, v1);
            else
                *(float2*)&ext_out[(size_t)gm2 * 64 + n0] = make_float2(v0, v1);
        }
    }
}

// ------------------------------------------------------------------
// launch: 0 zero  1 fill  2 pad  3 gemmA(profiled)  4 gather1  5 gemmB
//         6 gather2  7 gemmC
// ------------------------------------------------------------------
extern "C" void kernel_launch(void* const* d_in, const int* in_sizes, int n_in,
                              void* d_out, int out_size) {
    const float* x     = (const float*)d_in[0];
    const int*   ei    = (const int*)d_in[1];     // int32 edge indices
    const float* W_in  = (const float*)d_in[2];
    const float* b_in  = (const float*)d_in[3];
    const float* W1    = (const float*)d_in[4];
    const float* b1    = (const float*)d_in[5];
    const float* W2    = (const float*)d_in[6];
    const float* b2    = (const float*)d_in[7];
    const float* W_out = (const float*)d_in[8];
    const float* b_out = (const float*)d_in[9];
    float* out = (float*)d_out;

    int N = in_sizes[0] / 128;   // 100000
    int E = in_sizes[1] / 2;     // 1600000
    const int* e0 = ei;
    const int* e1 = ei + E;

    int tileBlocks = (N + 127) / 128;
    int gatherBlocks = (N + 7) / 8;

    zero_cnt_kernel<<<(N + 255) / 256, 256>>>(N);
    fill_adj_kernel<<<(E + 255) / 256, 256>>>(e0, e1, E);
    pad_adj_kernel<<<(N + 255) / 256, 256>>>(N);

    // fused tensor-core: h = x@W_in+b_in; g = dinv*relu(h@W1+b1) -> fp16; dinv
    gemm_fused_A<<<tileBlocks, 256>>>(x, W_in, b_in, W1, b1, N);

    // propagate 1
    gather_kernel<<<gatherBlocks, 256>>>(N);

    // g = dinv * relu((dinv*S)@W2 + b2) -> d_gh (fp16)  [tensor core]
    gemm_tc<BUF_S, true, true><<<tileBlocks, 256>>>(nullptr, W2, b2, N);

    // propagate 2
    gather_kernel<<<gatherBlocks, 256>>>(N);

    // out = (dinv*S) @ W_out + b_out  (fp32 out)  [tensor core]
    gemm_tc<BUF_EXT, false, false><<<tileBlocks, 256>>>(out, W_out, b_out, N);
}